// round 1
// baseline (speedup 1.0000x reference)
#include <cuda_runtime.h>
#include <cstddef>

// ---------------------------------------------------------------------------
// Sbox16: out = c + sum_seg M[:, seg*256 + argmax_seg(x@W1^T + b1)]
//   M = W3@W2 (128x4096), c = W3@b2 + b3
// Kernels:
//   1) transpose x -> xT[128][B], W1 -> W1T[128][4096], W3 -> W3T[4096][128]
//   2) c_kernel:  c[i] = sum_j W3[i][j]*b2[j] + b3[i]
//   3) m_kernel:  MT[k][i] = sum_j W3T[j][i]*W2[j][k]   (stored k-major for gather)
//   4) s1_kernel: o-tile GEMM (64 rows x 256 cols, K=128) + per-row argmax -> idx
//   5) gather_kernel: out[b][i] = c[i] + sum_seg MT[seg*256+idx[b][seg]][i]
// ---------------------------------------------------------------------------

static constexpr int BMAX = 32768;
static constexpr int D    = 128;    // input/output feature dim
static constexpr int H    = 4096;   // hidden dim
static constexpr int SEG  = 256;
static constexpr int NSEG = 16;

__device__ float g_xT [D * BMAX];        // [j][b]
__device__ float g_W1T[D * H];           // [j][c]
__device__ float g_W3T[H * D];           // [j][i]
__device__ float g_MT [H * D];           // [k][i]
__device__ float g_c  [D];
__device__ int   g_idx[BMAX * NSEG];     // [b][seg], relative col in 0..255

// -------------------------------- transpose -------------------------------
__global__ void transpose_kernel(const float* __restrict__ src,
                                 float* __restrict__ dst, int R, int C) {
    __shared__ float tile[32][33];
    int c0 = blockIdx.x * 32;
    int r0 = blockIdx.y * 32;
    int tx = threadIdx.x, ty = threadIdx.y;
    #pragma unroll
    for (int i = ty; i < 32; i += 8) {
        int r = r0 + i, cc = c0 + tx;
        if (r < R && cc < C) tile[i][tx] = src[(size_t)r * C + cc];
    }
    __syncthreads();
    #pragma unroll
    for (int i = ty; i < 32; i += 8) {
        int cr = c0 + i, rr = r0 + tx;
        if (cr < C && rr < R) dst[(size_t)cr * R + rr] = tile[tx][i];
    }
}

// ---------------------------------- c ------------------------------------
__global__ void c_kernel(const float* __restrict__ W3,
                         const float* __restrict__ b2,
                         const float* __restrict__ b3) {
    const int i = blockIdx.x;            // 0..127
    float s = 0.f;
    for (int j = threadIdx.x; j < H; j += 256)
        s += W3[(size_t)i * H + j] * b2[j];
    __shared__ float red[256];
    red[threadIdx.x] = s;
    __syncthreads();
    for (int o = 128; o > 0; o >>= 1) {
        if (threadIdx.x < o) red[threadIdx.x] += red[threadIdx.x + o];
        __syncthreads();
    }
    if (threadIdx.x == 0) g_c[i] = red[0] + b3[i];
}

// ------------------------------ M = W3 @ W2 -------------------------------
// Block: 128 i x 32 k output tile, K(=j)=4096 in chunks of 32. 256 threads,
// thread tile 8i x 2k. Grid: 4096/32 = 128 blocks.
__global__ __launch_bounds__(256) void m_kernel(const float* __restrict__ W2) {
    __shared__ float w3s[32][128];   // [jj][i]
    __shared__ float w2s[32][32];    // [jj][k]
    const int tid   = threadIdx.x;
    const int kbase = blockIdx.x * 32;
    const int ig = tid >> 4;         // 0..15 -> i0 = ig*8
    const int kg = tid & 15;         // 0..15 -> k0 = kg*2
    const int i0 = ig * 8;
    const int k0 = kg * 2;

    float acc[2][8];
    #pragma unroll
    for (int a = 0; a < 2; a++)
        #pragma unroll
        for (int b = 0; b < 8; b++) acc[a][b] = 0.f;

    for (int j0 = 0; j0 < H; j0 += 32) {
        __syncthreads();
        // w3s: 32x128 = 1024 float4, 4 per thread
        #pragma unroll
        for (int p = 0; p < 4; p++) {
            int q  = tid + p * 256;
            int jj = q >> 5;        // 32 float4 per row
            int i4 = q & 31;
            *(float4*)&w3s[jj][i4 * 4] =
                *(const float4*)&g_W3T[(size_t)(j0 + jj) * D + i4 * 4];
        }
        // w2s: 32x32 scalars, 4 per thread
        #pragma unroll
        for (int p = 0; p < 4; p++) {
            int q  = tid + p * 256;
            int jj = q >> 5;
            int kk = q & 31;
            w2s[jj][kk] = W2[(size_t)(j0 + jj) * H + kbase + kk];
        }
        __syncthreads();
        #pragma unroll
        for (int jj = 0; jj < 32; jj++) {
            float av[2];
            float bv[8];
            *(float2*)av       = *(float2*)&w2s[jj][k0];
            *(float4*)bv       = *(float4*)&w3s[jj][i0];
            *(float4*)(bv + 4) = *(float4*)&w3s[jj][i0 + 4];
            #pragma unroll
            for (int a = 0; a < 2; a++)
                #pragma unroll
                for (int b = 0; b < 8; b++)
                    acc[a][b] += av[a] * bv[b];
        }
    }
    #pragma unroll
    for (int a = 0; a < 2; a++) {
        int k = kbase + k0 + a;
        *(float4*)&g_MT[(size_t)k * D + i0] =
            make_float4(acc[a][0], acc[a][1], acc[a][2], acc[a][3]);
        *(float4*)&g_MT[(size_t)k * D + i0 + 4] =
            make_float4(acc[a][4], acc[a][5], acc[a][6], acc[a][7]);
    }
}

// ----------------------- stage 1 GEMM + segment argmax --------------------
// Block computes o[rowbase..rowbase+63][seg*256 .. seg*256+255], K=128.
// 512 threads: cg = tid&31 (8 cols each), rg = tid>>5 (4 rows each).
// Warp == one row-group -> shuffle argmax across the 256 columns.
__global__ __launch_bounds__(512, 2) void s1_kernel(const float* __restrict__ b1,
                                                    int B) {
    __shared__ float xs[32][64];     // [jj][r]
    __shared__ float ws[32][256];    // [jj][c]
    __shared__ float bs[256];
    const int tid     = threadIdx.x;
    const int rowbase = blockIdx.x * 64;
    const int seg     = blockIdx.y;
    const int segbase = seg << 8;
    const int cg = tid & 31;
    const int rg = tid >> 5;
    const int c0 = cg * 8;
    const int r0 = rg * 4;

    if (tid < 256) bs[tid] = b1[segbase + tid];

    float acc[4][8];
    #pragma unroll
    for (int a = 0; a < 4; a++)
        #pragma unroll
        for (int b = 0; b < 8; b++) acc[a][b] = 0.f;

    for (int j0 = 0; j0 < D; j0 += 32) {
        __syncthreads();
        // xs: 32x64 = 512 float4, 1 per thread
        {
            int jj = tid >> 4;       // 16 float4 per row
            int r4 = tid & 15;
            *(float4*)&xs[jj][r4 * 4] =
                *(const float4*)&g_xT[(size_t)(j0 + jj) * B + rowbase + r4 * 4];
        }
        // ws: 32x256 = 2048 float4, 4 per thread
        #pragma unroll
        for (int p = 0; p < 4; p++) {
            int q  = tid + p * 512;
            int jj = q >> 6;         // 64 float4 per row
            int c4 = q & 63;
            *(float4*)&ws[jj][c4 * 4] =
                *(const float4*)&g_W1T[(size_t)(j0 + jj) * H + segbase + c4 * 4];
        }
        __syncthreads();
        #pragma unroll
        for (int jj = 0; jj < 32; jj++) {
            float xv[4];
            float wv[8];
            *(float4*)xv       = *(float4*)&xs[jj][r0];
            *(float4*)wv       = *(float4*)&ws[jj][c0];
            *(float4*)(wv + 4) = *(float4*)&ws[jj][c0 + 4];
            #pragma unroll
            for (int a = 0; a < 4; a++)
                #pragma unroll
                for (int b = 0; b < 8; b++)
                    acc[a][b] += xv[a] * wv[b];
        }
    }

    // bias + argmax (first-index tie-break, matching jnp.argmax)
    #pragma unroll
    for (int rr = 0; rr < 4; rr++) {
        float v  = acc[rr][0] + bs[c0];
        int   li = c0;
        #pragma unroll
        for (int cc = 1; cc < 8; cc++) {
            float vv = acc[rr][cc] + bs[c0 + cc];
            if (vv > v) { v = vv; li = c0 + cc; }
        }
        #pragma unroll
        for (int off = 16; off > 0; off >>= 1) {
            float ov = __shfl_down_sync(0xffffffffu, v, off);
            int   oi = __shfl_down_sync(0xffffffffu, li, off);
            if (ov > v || (ov == v && oi < li)) { v = ov; li = oi; }
        }
        if (cg == 0)
            g_idx[(size_t)(rowbase + r0 + rr) * NSEG + seg] = li;
    }
}

// --------------------------------- gather ---------------------------------
// Block: 16 rows, 128 threads (one output column each).
__global__ __launch_bounds__(128) void gather_kernel(float* __restrict__ out,
                                                     int B) {
    const int rowbase = blockIdx.x * 16;
    const int t = threadIdx.x;
    __shared__ int sidx[16][16];
    #pragma unroll
    for (int q = t; q < 256; q += 128)
        sidx[q >> 4][q & 15] = g_idx[(size_t)(rowbase + (q >> 4)) * NSEG + (q & 15)];
    __syncthreads();

    const float cv = g_c[t];
    float acc[16];
    #pragma unroll
    for (int r = 0; r < 16; r++) acc[r] = cv;

    #pragma unroll
    for (int s = 0; s < NSEG; s++) {
        #pragma unroll
        for (int r = 0; r < 16; r++) {
            int col = (s << 8) + sidx[r][s];
            acc[r] += g_MT[(size_t)col * D + t];
        }
    }
    #pragma unroll
    for (int r = 0; r < 16; r++)
        out[(size_t)(rowbase + r) * D + t] = acc[r];
}

// ------------------------------- launcher ----------------------------------
extern "C" void kernel_launch(void* const* d_in, const int* in_sizes, int n_in,
                              void* d_out, int out_size) {
    const float* x  = (const float*)d_in[0];
    const float* W1 = (const float*)d_in[1];
    const float* b1 = (const float*)d_in[2];
    const float* W2 = (const float*)d_in[3];
    const float* b2 = (const float*)d_in[4];
    const float* W3 = (const float*)d_in[5];
    const float* b3 = (const float*)d_in[6];
    float* out = (float*)d_out;
    const int B = in_sizes[0] / D;   // 32768

    void *p_xT = nullptr, *p_W1T = nullptr, *p_W3T = nullptr;
    cudaGetSymbolAddress(&p_xT, g_xT);
    cudaGetSymbolAddress(&p_W1T, g_W1T);
    cudaGetSymbolAddress(&p_W3T, g_W3T);

    dim3 tb(32, 8);
    transpose_kernel<<<dim3(D / 32, B / 32), tb>>>(x,  (float*)p_xT,  B,  D);
    transpose_kernel<<<dim3(D / 32, H / 32), tb>>>(W1, (float*)p_W1T, H,  D);
    transpose_kernel<<<dim3(H / 32, D / 32), tb>>>(W3, (float*)p_W3T, D,  H);

    c_kernel<<<D, 256>>>(W3, b2, b3);
    m_kernel<<<H / 32, 256>>>(W2);
    s1_kernel<<<dim3(B / 64, NSEG), 512>>>(b1, B);
    gather_kernel<<<B / 16, 128>>>(out, B);
}

// round 2
// speedup vs baseline: 1.0400x; 1.0400x over previous
#include <cuda_runtime.h>
#include <cstddef>

// ---------------------------------------------------------------------------
// Sbox16: out = c + sum_seg M[:, seg*256 + argmax_seg(x@W1^T + b1)]
//   M = W3@W2 (128x4096), c = W3@b2 + b3
// R2: inner products use packed fma.rn.f32x2 (SASS FFMA2) -> 2x fp32 rate.
// ---------------------------------------------------------------------------

static constexpr int BMAX = 32768;
static constexpr int D    = 128;    // input/output feature dim
static constexpr int H    = 4096;   // hidden dim
static constexpr int SEG  = 256;
static constexpr int NSEG = 16;

__device__ float g_xT [D * BMAX];        // [j][b]
__device__ float g_W1T[D * H];           // [j][c]
__device__ float g_W3T[H * D];           // [j][i]
__device__ float g_MT [H * D];           // [k][i]
__device__ float g_c  [D];
__device__ int   g_idx[BMAX * NSEG];     // [b][seg], relative col in 0..255

// packed fp32x2 helpers ------------------------------------------------------
__device__ __forceinline__ unsigned long long dup_f32x2(float v) {
    unsigned long long r;
    asm("mov.b64 %0, {%1, %1};" : "=l"(r) : "f"(v));
    return r;
}
__device__ __forceinline__ void fma_f32x2(unsigned long long& d,
                                          unsigned long long a,
                                          unsigned long long b) {
    asm("fma.rn.f32x2 %0, %1, %2, %0;" : "+l"(d) : "l"(a), "l"(b));
}
__device__ __forceinline__ void unpack_f32x2(unsigned long long v,
                                             float& lo, float& hi) {
    asm("mov.b64 {%0, %1}, %2;" : "=f"(lo), "=f"(hi) : "l"(v));
}

// -------------------------------- transpose -------------------------------
__global__ void transpose_kernel(const float* __restrict__ src,
                                 float* __restrict__ dst, int R, int C) {
    __shared__ float tile[32][33];
    int c0 = blockIdx.x * 32;
    int r0 = blockIdx.y * 32;
    int tx = threadIdx.x, ty = threadIdx.y;
    #pragma unroll
    for (int i = ty; i < 32; i += 8) {
        int r = r0 + i, cc = c0 + tx;
        if (r < R && cc < C) tile[i][tx] = src[(size_t)r * C + cc];
    }
    __syncthreads();
    #pragma unroll
    for (int i = ty; i < 32; i += 8) {
        int cr = c0 + i, rr = r0 + tx;
        if (cr < C && rr < R) dst[(size_t)cr * R + rr] = tile[tx][i];
    }
}

// ---------------------------------- c ------------------------------------
__global__ void c_kernel(const float* __restrict__ W3,
                         const float* __restrict__ b2,
                         const float* __restrict__ b3) {
    const int i = blockIdx.x;            // 0..127
    float s = 0.f;
    for (int j = threadIdx.x; j < H; j += 256)
        s += W3[(size_t)i * H + j] * b2[j];
    __shared__ float red[256];
    red[threadIdx.x] = s;
    __syncthreads();
    for (int o = 128; o > 0; o >>= 1) {
        if (threadIdx.x < o) red[threadIdx.x] += red[threadIdx.x + o];
        __syncthreads();
    }
    if (threadIdx.x == 0) g_c[i] = red[0] + b3[i];
}

// ------------------------------ M = W3 @ W2 -------------------------------
// Block: 128 i x 32 k output tile, K(=j)=4096 in chunks of 32. 256 threads,
// thread tile 8i x 2k, FFMA2-packed along i. Grid: 4096/32 = 128 blocks.
__global__ __launch_bounds__(256) void m_kernel(const float* __restrict__ W2) {
    __shared__ float w3s[32][128];   // [jj][i]
    __shared__ float w2s[32][32];    // [jj][k]
    const int tid   = threadIdx.x;
    const int kbase = blockIdx.x * 32;
    const int ig = tid >> 4;         // 0..15 -> i0 = ig*8
    const int kg = tid & 15;         // 0..15 -> k0 = kg*2
    const int i0 = ig * 8;
    const int k0 = kg * 2;

    unsigned long long acc2[2][4];
    #pragma unroll
    for (int a = 0; a < 2; a++)
        #pragma unroll
        for (int p = 0; p < 4; p++) acc2[a][p] = 0ull;

    for (int j0 = 0; j0 < H; j0 += 32) {
        __syncthreads();
        // w3s: 32x128 = 1024 float4, 4 per thread
        #pragma unroll
        for (int p = 0; p < 4; p++) {
            int q  = tid + p * 256;
            int jj = q >> 5;        // 32 float4 per row
            int i4 = q & 31;
            *(float4*)&w3s[jj][i4 * 4] =
                *(const float4*)&g_W3T[(size_t)(j0 + jj) * D + i4 * 4];
        }
        // w2s: 32x32 scalars, 4 per thread
        #pragma unroll
        for (int p = 0; p < 4; p++) {
            int q  = tid + p * 256;
            int jj = q >> 5;
            int kk = q & 31;
            w2s[jj][kk] = W2[(size_t)(j0 + jj) * H + kbase + kk];
        }
        __syncthreads();
        #pragma unroll
        for (int jj = 0; jj < 32; jj++) {
            float2 av = *(float2*)&w2s[jj][k0];
            unsigned long long a2[2];
            a2[0] = dup_f32x2(av.x);
            a2[1] = dup_f32x2(av.y);
            ulonglong2 bq0 = *(ulonglong2*)&w3s[jj][i0];
            ulonglong2 bq1 = *(ulonglong2*)&w3s[jj][i0 + 4];
            unsigned long long b2v[4] = {bq0.x, bq0.y, bq1.x, bq1.y};
            #pragma unroll
            for (int a = 0; a < 2; a++)
                #pragma unroll
                for (int p = 0; p < 4; p++)
                    fma_f32x2(acc2[a][p], a2[a], b2v[p]);
        }
    }
    #pragma unroll
    for (int a = 0; a < 2; a++) {
        int k = kbase + k0 + a;
        float r[8];
        #pragma unroll
        for (int p = 0; p < 4; p++) unpack_f32x2(acc2[a][p], r[2*p], r[2*p+1]);
        *(float4*)&g_MT[(size_t)k * D + i0]     = make_float4(r[0], r[1], r[2], r[3]);
        *(float4*)&g_MT[(size_t)k * D + i0 + 4] = make_float4(r[4], r[5], r[6], r[7]);
    }
}

// ----------------------- stage 1 GEMM + segment argmax --------------------
// Block computes o[rowbase..rowbase+63][seg*256 .. seg*256+255], K=128.
// 512 threads: cg = tid&31 (8 cols each), rg = tid>>5 (4 rows each).
// FFMA2-packed along columns. Warp == one row-group -> shuffle argmax.
__global__ __launch_bounds__(512, 2) void s1_kernel(const float* __restrict__ b1,
                                                    int B) {
    __shared__ float xs[32][64];     // [jj][r]
    __shared__ float ws[32][256];    // [jj][c]
    __shared__ float bs[256];
    const int tid     = threadIdx.x;
    const int rowbase = blockIdx.x * 64;
    const int seg     = blockIdx.y;
    const int segbase = seg << 8;
    const int cg = tid & 31;
    const int rg = tid >> 5;
    const int c0 = cg * 8;
    const int r0 = rg * 4;

    if (tid < 256) bs[tid] = b1[segbase + tid];

    unsigned long long acc2[4][4];
    #pragma unroll
    for (int a = 0; a < 4; a++)
        #pragma unroll
        for (int p = 0; p < 4; p++) acc2[a][p] = 0ull;

    for (int j0 = 0; j0 < D; j0 += 32) {
        __syncthreads();
        // xs: 32x64 = 512 float4, 1 per thread
        {
            int jj = tid >> 4;       // 16 float4 per row
            int r4 = tid & 15;
            *(float4*)&xs[jj][r4 * 4] =
                *(const float4*)&g_xT[(size_t)(j0 + jj) * B + rowbase + r4 * 4];
        }
        // ws: 32x256 = 2048 float4, 4 per thread
        #pragma unroll
        for (int p = 0; p < 4; p++) {
            int q  = tid + p * 512;
            int jj = q >> 6;         // 64 float4 per row
            int c4 = q & 63;
            *(float4*)&ws[jj][c4 * 4] =
                *(const float4*)&g_W1T[(size_t)(j0 + jj) * H + segbase + c4 * 4];
        }
        __syncthreads();
        #pragma unroll
        for (int jj = 0; jj < 32; jj++) {
            float4 xv = *(float4*)&xs[jj][r0];
            unsigned long long x2[4];
            x2[0] = dup_f32x2(xv.x);
            x2[1] = dup_f32x2(xv.y);
            x2[2] = dup_f32x2(xv.z);
            x2[3] = dup_f32x2(xv.w);
            ulonglong2 wq0 = *(ulonglong2*)&ws[jj][c0];
            ulonglong2 wq1 = *(ulonglong2*)&ws[jj][c0 + 4];
            unsigned long long w2v[4] = {wq0.x, wq0.y, wq1.x, wq1.y};
            #pragma unroll
            for (int a = 0; a < 4; a++)
                #pragma unroll
                for (int p = 0; p < 4; p++)
                    fma_f32x2(acc2[a][p], x2[a], w2v[p]);
        }
    }

    // bias + argmax (first-index tie-break, matching jnp.argmax)
    #pragma unroll
    for (int rr = 0; rr < 4; rr++) {
        float v  = -3.402823466e+38f;
        int   li = c0;
        #pragma unroll
        for (int p = 0; p < 4; p++) {
            float lo, hi;
            unpack_f32x2(acc2[rr][p], lo, hi);
            float v0 = lo + bs[c0 + 2 * p];
            float v1 = hi + bs[c0 + 2 * p + 1];
            if (v0 > v) { v = v0; li = c0 + 2 * p; }
            if (v1 > v) { v = v1; li = c0 + 2 * p + 1; }
        }
        #pragma unroll
        for (int off = 16; off > 0; off >>= 1) {
            float ov = __shfl_down_sync(0xffffffffu, v, off);
            int   oi = __shfl_down_sync(0xffffffffu, li, off);
            if (ov > v || (ov == v && oi < li)) { v = ov; li = oi; }
        }
        if (cg == 0)
            g_idx[(size_t)(rowbase + r0 + rr) * NSEG + seg] = li;
    }
}

// --------------------------------- gather ---------------------------------
// Block: 16 rows, 128 threads (one output column each).
__global__ __launch_bounds__(128) void gather_kernel(float* __restrict__ out,
                                                     int B) {
    const int rowbase = blockIdx.x * 16;
    const int t = threadIdx.x;
    __shared__ int sidx[16][16];
    #pragma unroll
    for (int q = t; q < 256; q += 128)
        sidx[q >> 4][q & 15] = g_idx[(size_t)(rowbase + (q >> 4)) * NSEG + (q & 15)];
    __syncthreads();

    const float cv = g_c[t];
    float acc[16];
    #pragma unroll
    for (int r = 0; r < 16; r++) acc[r] = cv;

    #pragma unroll
    for (int s = 0; s < NSEG; s++) {
        #pragma unroll
        for (int r = 0; r < 16; r++) {
            int col = (s << 8) + sidx[r][s];
            acc[r] += g_MT[(size_t)col * D + t];
        }
    }
    #pragma unroll
    for (int r = 0; r < 16; r++)
        out[(size_t)(rowbase + r) * D + t] = acc[r];
}

// ------------------------------- launcher ----------------------------------
extern "C" void kernel_launch(void* const* d_in, const int* in_sizes, int n_in,
                              void* d_out, int out_size) {
    const float* x  = (const float*)d_in[0];
    const float* W1 = (const float*)d_in[1];
    const float* b1 = (const float*)d_in[2];
    const float* W2 = (const float*)d_in[3];
    const float* b2 = (const float*)d_in[4];
    const float* W3 = (const float*)d_in[5];
    const float* b3 = (const float*)d_in[6];
    float* out = (float*)d_out;
    const int B = in_sizes[0] / D;   // 32768

    void *p_xT = nullptr, *p_W1T = nullptr, *p_W3T = nullptr;
    cudaGetSymbolAddress(&p_xT, g_xT);
    cudaGetSymbolAddress(&p_W1T, g_W1T);
    cudaGetSymbolAddress(&p_W3T, g_W3T);

    dim3 tb(32, 8);
    transpose_kernel<<<dim3(D / 32, B / 32), tb>>>(x,  (float*)p_xT,  B,  D);
    transpose_kernel<<<dim3(D / 32, H / 32), tb>>>(W1, (float*)p_W1T, H,  D);
    transpose_kernel<<<dim3(H / 32, D / 32), tb>>>(W3, (float*)p_W3T, D,  H);

    c_kernel<<<D, 256>>>(W3, b2, b3);
    m_kernel<<<H / 32, 256>>>(W2);
    s1_kernel<<<dim3(B / 64, NSEG), 512>>>(b1, B);
    gather_kernel<<<B / 16, 128>>>(out, B);
}

// round 4
// speedup vs baseline: 1.7400x; 1.6731x over previous
#include <cuda_runtime.h>
#include <cuda_bf16.h>
#include <cstdint>
#include <cstddef>

// ---------------------------------------------------------------------------
// Sbox16: out = c + sum_seg M[:, seg*256 + argmax_seg(x@W1^T + b1)]
//   M = W3@W2 (128x4096), c = W3@b2 + b3
// R4: stage-1 via mma.sync bf16 (family-generic PTX; tcgen05 is sm_103a-only
//     and the harness targets compute_103). Approximate bf16 ranking + exact
//     fp32 rescore of columns within TAU of the approx max.
// ---------------------------------------------------------------------------

static constexpr int BMAX = 32768;
static constexpr int D    = 128;
static constexpr int H    = 4096;
static constexpr int NSEG = 16;
static constexpr float TAU = 0.13f;

__device__ __nv_bfloat16 g_xb [BMAX * D];   // bf16(x), row-major
__device__ __nv_bfloat16 g_w1b[H * D];      // bf16(W1), row-major
__device__ float g_W3T[H * D];
__device__ float g_MT [H * D];
__device__ float g_c  [D];
__device__ int   g_idx[BMAX * NSEG];

// ------------------------------- ptx helpers -------------------------------
__device__ __forceinline__ uint32_t smem_u32(const void* p) {
    uint32_t a;
    asm("{ .reg .u64 t; cvta.to.shared.u64 t, %1; cvt.u32.u64 %0, t; }" : "=r"(a) : "l"(p));
    return a;
}
__device__ __forceinline__ void ldsm_x4(uint32_t* r, uint32_t addr) {
    asm volatile("ldmatrix.sync.aligned.m8n8.x4.shared.b16 {%0,%1,%2,%3}, [%4];"
                 : "=r"(r[0]), "=r"(r[1]), "=r"(r[2]), "=r"(r[3]) : "r"(addr));
}
__device__ __forceinline__ void mma_bf16(float* d, const uint32_t* a,
                                         uint32_t b0, uint32_t b1) {
    asm volatile("mma.sync.aligned.m16n8k16.row.col.f32.bf16.bf16.f32 "
                 "{%0,%1,%2,%3}, {%4,%5,%6,%7}, {%8,%9}, {%0,%1,%2,%3};"
                 : "+f"(d[0]), "+f"(d[1]), "+f"(d[2]), "+f"(d[3])
                 : "r"(a[0]), "r"(a[1]), "r"(a[2]), "r"(a[3]), "r"(b0), "r"(b1));
}
__device__ __forceinline__ uint32_t ford(float f) {
    uint32_t u = __float_as_uint(f);
    return (u & 0x80000000u) ? ~u : (u | 0x80000000u);
}

// ------------------------------ bf16 convert -------------------------------
__global__ __launch_bounds__(256) void convertb_kernel(const float* __restrict__ src,
                                                       __nv_bfloat16* __restrict__ dst,
                                                       int n8) {
    int i = blockIdx.x * 256 + threadIdx.x;
    if (i >= n8) return;
    const float4* s4 = (const float4*)src;
    float4 a = s4[i * 2], b = s4[i * 2 + 1];
    __nv_bfloat162 p0 = __float22bfloat162_rn(make_float2(a.x, a.y));
    __nv_bfloat162 p1 = __float22bfloat162_rn(make_float2(a.z, a.w));
    __nv_bfloat162 p2 = __float22bfloat162_rn(make_float2(b.x, b.y));
    __nv_bfloat162 p3 = __float22bfloat162_rn(make_float2(b.z, b.w));
    uint4 o;
    o.x = *(uint32_t*)&p0; o.y = *(uint32_t*)&p1;
    o.z = *(uint32_t*)&p2; o.w = *(uint32_t*)&p3;
    ((uint4*)dst)[i] = o;
}

// -------------------------------- transpose -------------------------------
__global__ void transpose_kernel(const float* __restrict__ src,
                                 float* __restrict__ dst, int R, int C) {
    __shared__ float tile[32][33];
    int c0 = blockIdx.x * 32;
    int r0 = blockIdx.y * 32;
    int tx = threadIdx.x, ty = threadIdx.y;
    #pragma unroll
    for (int i = ty; i < 32; i += 8) {
        int r = r0 + i, cc = c0 + tx;
        if (r < R && cc < C) tile[i][tx] = src[(size_t)r * C + cc];
    }
    __syncthreads();
    #pragma unroll
    for (int i = ty; i < 32; i += 8) {
        int cr = c0 + i, rr = r0 + tx;
        if (cr < C && rr < R) dst[(size_t)cr * R + rr] = tile[tx][i];
    }
}

// ---------------------------------- c ------------------------------------
__global__ void c_kernel(const float* __restrict__ W3,
                         const float* __restrict__ b2,
                         const float* __restrict__ b3) {
    const int i = blockIdx.x;
    float s = 0.f;
    for (int j = threadIdx.x; j < H; j += 256)
        s += W3[(size_t)i * H + j] * b2[j];
    __shared__ float red[256];
    red[threadIdx.x] = s;
    __syncthreads();
    for (int o = 128; o > 0; o >>= 1) {
        if (threadIdx.x < o) red[threadIdx.x] += red[threadIdx.x + o];
        __syncthreads();
    }
    if (threadIdx.x == 0) g_c[i] = red[0] + b3[i];
}

// ------------------------------ M = W3 @ W2 -------------------------------
__global__ __launch_bounds__(256) void m_kernel(const float* __restrict__ W2) {
    __shared__ float w3s[32][128];
    __shared__ float w2s[32][32];
    const int tid   = threadIdx.x;
    const int kbase = blockIdx.x * 32;
    const int i0 = (tid >> 4) * 8;
    const int k0 = (tid & 15) * 2;

    float acc[2][8];
    #pragma unroll
    for (int a = 0; a < 2; a++)
        #pragma unroll
        for (int b = 0; b < 8; b++) acc[a][b] = 0.f;

    for (int j0 = 0; j0 < H; j0 += 32) {
        __syncthreads();
        #pragma unroll
        for (int p = 0; p < 4; p++) {
            int q  = tid + p * 256;
            int jj = q >> 5;
            int i4 = q & 31;
            *(float4*)&w3s[jj][i4 * 4] =
                *(const float4*)&g_W3T[(size_t)(j0 + jj) * D + i4 * 4];
        }
        #pragma unroll
        for (int p = 0; p < 4; p++) {
            int q = tid + p * 256;
            w2s[q >> 5][q & 31] = W2[(size_t)(j0 + (q >> 5)) * H + kbase + (q & 31)];
        }
        __syncthreads();
        #pragma unroll
        for (int jj = 0; jj < 32; jj++) {
            float av[2];
            float bv[8];
            *(float2*)av       = *(float2*)&w2s[jj][k0];
            *(float4*)bv       = *(float4*)&w3s[jj][i0];
            *(float4*)(bv + 4) = *(float4*)&w3s[jj][i0 + 4];
            #pragma unroll
            for (int a = 0; a < 2; a++)
                #pragma unroll
                for (int b = 0; b < 8; b++)
                    acc[a][b] += av[a] * bv[b];
        }
    }
    #pragma unroll
    for (int a = 0; a < 2; a++) {
        int k = kbase + k0 + a;
        *(float4*)&g_MT[(size_t)k * D + i0]     = make_float4(acc[a][0], acc[a][1], acc[a][2], acc[a][3]);
        *(float4*)&g_MT[(size_t)k * D + i0 + 4] = make_float4(acc[a][4], acc[a][5], acc[a][6], acc[a][7]);
    }
}

// ------------------ stage-1 mma.sync GEMM + argmax + rescore ----------------
// CTA: 128 rows (x tile) x 256 cols (one segment), K=128. 256 thr, 8 warps
// (2 row x 4 col), warp tile 64x64. bf16 approx rank; exact fp32 rescore of
// candidates within TAU of approx row max.
static constexpr int LIST_CAP = 2048;
// smem offsets (bytes)
static constexpr int OFF_A    = 0;                  // 128 x 136 bf16 = 34816
static constexpr int OFF_B    = 34816;              // 256 x 136 bf16 = 69632
static constexpr int OFF_BS   = 104448;             // float[256]
static constexpr int OFF_RM4  = 105472;             // float[128][4]
static constexpr int OFF_RMF  = 107520;             // float[128]
static constexpr int OFF_KB   = 108032;             // ull[128]
static constexpr int OFF_CNT  = 109056;             // int
static constexpr int OFF_LIST = 109072;             // u32[LIST_CAP]
static constexpr int S1_SMEM  = OFF_LIST + LIST_CAP * 4;

__global__ __launch_bounds__(256, 1) void s1mma_kernel(const float* __restrict__ x,
                                                       const float* __restrict__ W1,
                                                       const float* __restrict__ b1) {
    extern __shared__ char sm[];
    const int tid  = threadIdx.x;
    const int lane = tid & 31;
    const int wid  = tid >> 5;
    const int wr   = wid >> 2;      // warp row 0..1
    const int wc   = wid & 3;       // warp col 0..3
    const int tile = blockIdx.x;
    const int seg  = blockIdx.y;

    uint4* As4 = (uint4*)(sm + OFF_A);
    uint4* Bs4 = (uint4*)(sm + OFF_B);
    float* bs  = (float*)(sm + OFF_BS);
    float (*rm4)[4] = (float(*)[4])(sm + OFF_RM4);
    float* rmf = (float*)(sm + OFF_RMF);
    unsigned long long* kb = (unsigned long long*)(sm + OFF_KB);
    int* cnt = (int*)(sm + OFF_CNT);
    uint32_t* list = (uint32_t*)(sm + OFF_LIST);

    bs[tid] = b1[seg * 256 + tid];
    if (tid < 128) kb[tid] = 0ull;
    if (tid == 0) *cnt = 0;

    // load A (128x128 bf16), row stride 136 elems = 17 uint4
    const uint4* xb4 = (const uint4*)g_xb + (size_t)tile * 128 * 16;
    #pragma unroll
    for (int i = 0; i < 8; i++) {
        int q = tid + i * 256;
        int r = q >> 4, c = q & 15;
        As4[r * 17 + c] = xb4[r * 16 + c];
    }
    // load B (256x128 bf16)
    const uint4* wb4 = (const uint4*)g_w1b + (size_t)seg * 256 * 16;
    #pragma unroll
    for (int i = 0; i < 16; i++) {
        int q = tid + i * 256;
        int r = q >> 4, c = q & 15;
        Bs4[r * 17 + c] = wb4[r * 16 + c];
    }
    __syncthreads();

    const uint32_t sA = smem_u32(sm) + OFF_A;
    const uint32_t sB = smem_u32(sm) + OFF_B;
    // ldmatrix lane addresses
    const uint32_t addrA0 = sA + (uint32_t)(wr * 64 + (lane & 15)) * 272
                               + (uint32_t)(lane >> 4) * 16;
    const uint32_t addrB0 = sB + (uint32_t)(wc * 64 + (lane & 7) + ((lane >> 4) << 3)) * 272
                               + (uint32_t)((lane >> 3) & 1) * 16;

    float acc[4][8][4];
    #pragma unroll
    for (int mt = 0; mt < 4; mt++)
        #pragma unroll
        for (int nt = 0; nt < 8; nt++)
            #pragma unroll
            for (int e = 0; e < 4; e++) acc[mt][nt][e] = 0.f;

    #pragma unroll
    for (int ks = 0; ks < 8; ks++) {
        uint32_t a[4][4], b[4][4];
        #pragma unroll
        for (int mt = 0; mt < 4; mt++)
            ldsm_x4(a[mt], addrA0 + mt * (16 * 272) + ks * 32);
        #pragma unroll
        for (int g = 0; g < 4; g++)
            ldsm_x4(b[g], addrB0 + g * (16 * 272) + ks * 32);
        #pragma unroll
        for (int mt = 0; mt < 4; mt++)
            #pragma unroll
            for (int n8 = 0; n8 < 8; n8++)
                mma_bf16(acc[mt][n8], a[mt], b[n8 >> 1][(n8 & 1) * 2],
                         b[n8 >> 1][(n8 & 1) * 2 + 1]);
    }

    // ---------------- pass 1: approx row max over 256 cols -----------------
    const int q  = lane >> 2;
    const int qt = lane & 3;
    #pragma unroll
    for (int mt = 0; mt < 4; mt++) {
        #pragma unroll
        for (int h = 0; h < 2; h++) {
            float vm = -3.402823466e+38f;
            #pragma unroll
            for (int nt = 0; nt < 8; nt++)
                #pragma unroll
                for (int c = 0; c < 2; c++) {
                    float v = acc[mt][nt][h * 2 + c] + bs[wc * 64 + nt * 8 + qt * 2 + c];
                    vm = fmaxf(vm, v);
                }
            vm = fmaxf(vm, __shfl_xor_sync(0xffffffffu, vm, 1));
            vm = fmaxf(vm, __shfl_xor_sync(0xffffffffu, vm, 2));
            if (qt == 0) rm4[wr * 64 + mt * 16 + h * 8 + q][wc] = vm;
        }
    }
    __syncthreads();
    if (tid < 128)
        rmf[tid] = fmaxf(fmaxf(rm4[tid][0], rm4[tid][1]),
                         fmaxf(rm4[tid][2], rm4[tid][3]));
    __syncthreads();

    // ---------------- pass 2: collect candidates ---------------------------
    #pragma unroll
    for (int mt = 0; mt < 4; mt++)
        #pragma unroll
        for (int h = 0; h < 2; h++) {
            int rl = wr * 64 + mt * 16 + h * 8 + q;
            float thr = rmf[rl] - TAU;
            #pragma unroll
            for (int nt = 0; nt < 8; nt++)
                #pragma unroll
                for (int c = 0; c < 2; c++) {
                    int cs = wc * 64 + nt * 8 + qt * 2 + c;
                    float v = acc[mt][nt][h * 2 + c] + bs[cs];
                    if (v >= thr) {
                        int p = atomicAdd(cnt, 1);
                        if (p < LIST_CAP) list[p] = ((uint32_t)rl << 8) | (uint32_t)cs;
                    }
                }
        }
    __syncthreads();

    // ---------------- rescore candidates exactly (fp32) --------------------
    int n = *cnt;
    if (n > LIST_CAP) n = LIST_CAP;
    for (int i = wid; i < n; i += 8) {
        uint32_t e = list[i];
        int rl = e >> 8, cs = e & 255;
        const float4* xr = (const float4*)(x  + (size_t)(tile * 128 + rl) * 128);
        const float4* wv = (const float4*)(W1 + (size_t)(seg * 256 + cs) * 128);
        float4 xa = __ldg(&xr[lane]);
        float4 wa = __ldg(&wv[lane]);
        float s = xa.x * wa.x + xa.y * wa.y + xa.z * wa.z + xa.w * wa.w;
        #pragma unroll
        for (int off = 16; off > 0; off >>= 1)
            s += __shfl_xor_sync(0xffffffffu, s, off);
        if (lane == 0) {
            float val = s + bs[cs];
            unsigned long long key =
                ((unsigned long long)ford(val) << 32) | (uint32_t)(255 - cs);
            atomicMax(&kb[rl], key);
        }
    }
    __syncthreads();

    if (tid < 128) {
        int col = 255 - (int)(kb[tid] & 0xFFu);
        g_idx[(size_t)(tile * 128 + tid) * NSEG + seg] = col;
    }
}

// --------------------------------- gather ---------------------------------
__global__ __launch_bounds__(128) void gather_kernel(float* __restrict__ out) {
    const int rowbase = blockIdx.x * 16;
    const int t = threadIdx.x;
    __shared__ int sidx[16][16];
    #pragma unroll
    for (int qq = t; qq < 256; qq += 128)
        sidx[qq >> 4][qq & 15] = g_idx[(size_t)(rowbase + (qq >> 4)) * NSEG + (qq & 15)];
    __syncthreads();

    const float cv = g_c[t];
    float acc[16];
    #pragma unroll
    for (int r = 0; r < 16; r++) acc[r] = cv;

    #pragma unroll
    for (int s = 0; s < NSEG; s++) {
        #pragma unroll
        for (int r = 0; r < 16; r++) {
            int col = (s << 8) + sidx[r][s];
            acc[r] += g_MT[(size_t)col * D + t];
        }
    }
    #pragma unroll
    for (int r = 0; r < 16; r++)
        out[(size_t)(rowbase + r) * D + t] = acc[r];
}

// ------------------------------- launcher ----------------------------------
extern "C" void kernel_launch(void* const* d_in, const int* in_sizes, int n_in,
                              void* d_out, int out_size) {
    const float* x  = (const float*)d_in[0];
    const float* W1 = (const float*)d_in[1];
    const float* b1 = (const float*)d_in[2];
    const float* W2 = (const float*)d_in[3];
    const float* b2 = (const float*)d_in[4];
    const float* W3 = (const float*)d_in[5];
    const float* b3 = (const float*)d_in[6];
    float* out = (float*)d_out;
    const int B = in_sizes[0] / D;   // 32768

    void *p_xb = nullptr, *p_w1b = nullptr, *p_W3T = nullptr;
    cudaGetSymbolAddress(&p_xb,  g_xb);
    cudaGetSymbolAddress(&p_w1b, g_w1b);
    cudaGetSymbolAddress(&p_W3T, g_W3T);

    cudaFuncSetAttribute(s1mma_kernel,
                         cudaFuncAttributeMaxDynamicSharedMemorySize, S1_SMEM);

    convertb_kernel<<<(B * D / 8 + 255) / 256, 256>>>(x,  (__nv_bfloat16*)p_xb,  B * D / 8);
    convertb_kernel<<<(H * D / 8 + 255) / 256, 256>>>(W1, (__nv_bfloat16*)p_w1b, H * D / 8);

    dim3 tb(32, 8);
    transpose_kernel<<<dim3(H / 32, D / 32), tb>>>(W3, (float*)p_W3T, D, H);
    c_kernel<<<D, 256>>>(W3, b2, b3);
    m_kernel<<<H / 32, 256>>>(W2);

    s1mma_kernel<<<dim3(B / 128, NSEG), 256, S1_SMEM>>>(x, W1, b1);
    gather_kernel<<<B / 16, 128>>>(out);
}

// round 5
// speedup vs baseline: 2.4797x; 1.4251x over previous
#include <cuda_runtime.h>
#include <cuda_bf16.h>
#include <cstdint>
#include <cstddef>

// ---------------------------------------------------------------------------
// Sbox16: out = c + sum_seg M[:, seg*256 + argmax_seg(x@W1^T + b1)]
//   M = W3@W2 (128x4096), c = W3@b2 + b3
// R5: s1 at occupancy 2 (swizzled smem, 128x128 CTA tiles, global key-merge);
//     M on mma.sync via 2-term bf16 split (3 products) + deterministic reduce.
// ---------------------------------------------------------------------------

static constexpr int BMAX = 32768;
static constexpr int D    = 128;
static constexpr int H    = 4096;
static constexpr int NSEG = 16;
static constexpr float TAU = 0.13f;

__device__ __nv_bfloat16 g_xb [BMAX * D];            // bf16(x) row-major
__device__ __nv_bfloat16 g_w1b[H * D];               // bf16(W1) row-major
__device__ __nv_bfloat16 g_w2t[2 * (size_t)H * H];   // [term][k][j] = W2[j][k] split
__device__ __nv_bfloat16 g_w3b[2 * H * D / 32 * 32]; // [term][i][j] split of W3
__device__ float g_mpart[8 * H * D];                 // [jsplit][k][i]
__device__ float g_MT [H * D];                       // [k][i]
__device__ float g_c  [D];
__device__ unsigned long long g_kb[BMAX * NSEG];     // (ford(val)<<32)|(255-col)

// ------------------------------- ptx helpers -------------------------------
__device__ __forceinline__ uint32_t smem_u32(const void* p) {
    uint32_t a;
    asm("{ .reg .u64 t; cvta.to.shared.u64 t, %1; cvt.u32.u64 %0, t; }" : "=r"(a) : "l"(p));
    return a;
}
__device__ __forceinline__ void ldsm_x4(uint32_t* r, uint32_t addr) {
    asm volatile("ldmatrix.sync.aligned.m8n8.x4.shared.b16 {%0,%1,%2,%3}, [%4];"
                 : "=r"(r[0]), "=r"(r[1]), "=r"(r[2]), "=r"(r[3]) : "r"(addr));
}
__device__ __forceinline__ void mma_bf16(float* d, const uint32_t* a,
                                         uint32_t b0, uint32_t b1) {
    asm volatile("mma.sync.aligned.m16n8k16.row.col.f32.bf16.bf16.f32 "
                 "{%0,%1,%2,%3}, {%4,%5,%6,%7}, {%8,%9}, {%0,%1,%2,%3};"
                 : "+f"(d[0]), "+f"(d[1]), "+f"(d[2]), "+f"(d[3])
                 : "r"(a[0]), "r"(a[1]), "r"(a[2]), "r"(a[3]), "r"(b0), "r"(b1));
}
__device__ __forceinline__ uint32_t ford(float f) {
    uint32_t u = __float_as_uint(f);
    return (u & 0x80000000u) ? ~u : (u | 0x80000000u);
}

// ------------------------------ prepasses ----------------------------------
__global__ __launch_bounds__(256) void convertb_kernel(const float* __restrict__ src,
                                                       __nv_bfloat16* __restrict__ dst,
                                                       int n8) {
    int i = blockIdx.x * 256 + threadIdx.x;
    if (i >= n8) return;
    const float4* s4 = (const float4*)src;
    float4 a = s4[i * 2], b = s4[i * 2 + 1];
    __nv_bfloat162 p0 = __float22bfloat162_rn(make_float2(a.x, a.y));
    __nv_bfloat162 p1 = __float22bfloat162_rn(make_float2(a.z, a.w));
    __nv_bfloat162 p2 = __float22bfloat162_rn(make_float2(b.x, b.y));
    __nv_bfloat162 p3 = __float22bfloat162_rn(make_float2(b.z, b.w));
    uint4 o;
    o.x = *(uint32_t*)&p0; o.y = *(uint32_t*)&p1;
    o.z = *(uint32_t*)&p2; o.w = *(uint32_t*)&p3;
    ((uint4*)dst)[i] = o;
}

// W3 2-term split, layout preserved ([i][j], j contiguous)
__global__ __launch_bounds__(256) void w3split_kernel(const float* __restrict__ W3) {
    int i = blockIdx.x * 256 + threadIdx.x;       // handles 2 elements
    if (i >= H * D / 2) return;
    float2 v = ((const float2*)W3)[i];
    __nv_bfloat16 a0 = __float2bfloat16(v.x);
    __nv_bfloat16 b0 = __float2bfloat16(v.x - __bfloat162float(a0));
    __nv_bfloat16 a1 = __float2bfloat16(v.y);
    __nv_bfloat16 b1 = __float2bfloat16(v.y - __bfloat162float(a1));
    __nv_bfloat162 pa = {a0, a1}, pb = {b0, b1};
    ((__nv_bfloat162*)g_w3b)[i] = pa;
    ((__nv_bfloat162*)g_w3b)[H * D / 2 + i] = pb;
}

// W2 transpose + 2-term split: g_w2t[term][k][j] = split(W2[j][k])
__global__ void w2split_kernel(const float* __restrict__ W2) {
    __shared__ float tile[32][33];
    int k0 = blockIdx.x * 32;
    int j0 = blockIdx.y * 32;
    int tx = threadIdx.x, ty = threadIdx.y;
    #pragma unroll
    for (int i = ty; i < 32; i += 8)
        tile[i][tx] = W2[(size_t)(j0 + i) * H + k0 + tx];   // tile[jj][kk]
    __syncthreads();
    if (tx < 16) {
        #pragma unroll
        for (int i = ty; i < 32; i += 8) {
            float v0 = tile[2 * tx][i];
            float v1 = tile[2 * tx + 1][i];
            __nv_bfloat16 a0 = __float2bfloat16(v0);
            __nv_bfloat16 b0 = __float2bfloat16(v0 - __bfloat162float(a0));
            __nv_bfloat16 a1 = __float2bfloat16(v1);
            __nv_bfloat16 b1 = __float2bfloat16(v1 - __bfloat162float(a1));
            __nv_bfloat162 pa = {a0, a1}, pb = {b0, b1};
            size_t off = (size_t)(k0 + i) * H + j0 + 2 * tx;
            *(__nv_bfloat162*)(g_w2t + off) = pa;
            *(__nv_bfloat162*)(g_w2t + (size_t)H * H + off) = pb;
        }
    }
}

__global__ __launch_bounds__(256) void kbinit_kernel() {
    int i = blockIdx.x * 256 + threadIdx.x;
    if (i < BMAX * NSEG) g_kb[i] = 0ull;
}

// ---------------------------------- c ------------------------------------
__global__ void c_kernel(const float* __restrict__ W3,
                         const float* __restrict__ b2,
                         const float* __restrict__ b3) {
    const int i = blockIdx.x;
    float s = 0.f;
    for (int j = threadIdx.x; j < H; j += 256)
        s += W3[(size_t)i * H + j] * b2[j];
    __shared__ float red[256];
    red[threadIdx.x] = s;
    __syncthreads();
    for (int o = 128; o > 0; o >>= 1) {
        if (threadIdx.x < o) red[threadIdx.x] += red[threadIdx.x + o];
        __syncthreads();
    }
    if (threadIdx.x == 0) g_c[i] = red[0] + b3[i];
}

// ----------------- M via mma.sync: MT[k][i] = sum_j W2[j][k]W3[i][j] --------
// grid (32 k-tiles, 8 j-splits), 256 thr (warps 2x4), CTA out 128k x 128i,
// per-CTA j range = 512 in chunks of 64. 3 bf16 products (a0b0,a0b1,a1b0).
static constexpr int MM_SMEM = 65536;   // A 2x16KB + B 2x16KB, swizzled 128B rows

__global__ __launch_bounds__(256, 2) void mm2_kernel() {
    extern __shared__ char sm[];
    const int tid  = threadIdx.x;
    const int lane = tid & 31;
    const int wid  = tid >> 5;
    const int wr   = wid >> 2;
    const int wc   = wid & 3;
    const int k0   = blockIdx.x * 128;
    const int j0   = blockIdx.y * 512;

    const uint32_t sA = smem_u32(sm);
    const uint32_t sB = sA + 32768;

    float acc[4][4][4];
    #pragma unroll
    for (int mt = 0; mt < 4; mt++)
        #pragma unroll
        for (int nt = 0; nt < 4; nt++)
            #pragma unroll
            for (int e = 0; e < 4; e++) acc[mt][nt][e] = 0.f;

    for (int jc = 0; jc < 8; jc++) {
        __syncthreads();
        // A: w2t terms [k0..+128][j0+jc*64..+64]
        #pragma unroll
        for (int t = 0; t < 2; t++) {
            const __nv_bfloat16* srcA = g_w2t + (size_t)t * H * H
                                      + (size_t)k0 * H + j0 + jc * 64;
            #pragma unroll
            for (int i = 0; i < 4; i++) {
                int q = tid + i * 256;
                int r = q >> 3, c = q & 7;
                *(uint4*)(sm + t * 16384 + r * 128 + (((c ^ (r & 7)) & 7) << 4)) =
                    *(const uint4*)(srcA + (size_t)r * H + c * 8);
            }
        }
        // B: w3b terms [0..128 i][same j]
        #pragma unroll
        for (int t = 0; t < 2; t++) {
            const __nv_bfloat16* srcB = g_w3b + (size_t)t * H * D
                                      + j0 + jc * 64;
            #pragma unroll
            for (int i = 0; i < 4; i++) {
                int q = tid + i * 256;
                int r = q >> 3, c = q & 7;
                *(uint4*)(sm + 32768 + t * 16384 + r * 128 + (((c ^ (r & 7)) & 7) << 4)) =
                    *(const uint4*)(srcB + (size_t)r * H + c * 8);
            }
        }
        __syncthreads();

        #pragma unroll
        for (int ks = 0; ks < 4; ks++) {
            uint32_t b0[2][4], b1[2][4], a[4][4];
            #pragma unroll
            for (int g = 0; g < 2; g++) {
                int r = wc * 32 + g * 16 + (lane & 7) + ((lane >> 4) << 3);
                int c = ks * 2 + ((lane >> 3) & 1);
                uint32_t sw = (uint32_t)((c ^ (r & 7)) & 7) << 4;
                ldsm_x4(b0[g], sB + r * 128 + sw);
                ldsm_x4(b1[g], sB + 16384 + r * 128 + sw);
            }
            // term a0 with b0 and b1
            #pragma unroll
            for (int mt = 0; mt < 4; mt++) {
                int r = wr * 64 + mt * 16 + (lane & 15);
                int c = ks * 2 + (lane >> 4);
                ldsm_x4(a[mt], sA + r * 128 + ((uint32_t)((c ^ (r & 7)) & 7) << 4));
            }
            #pragma unroll
            for (int mt = 0; mt < 4; mt++)
                #pragma unroll
                for (int n8 = 0; n8 < 4; n8++) {
                    mma_bf16(acc[mt][n8], a[mt], b0[n8 >> 1][(n8 & 1) * 2],
                             b0[n8 >> 1][(n8 & 1) * 2 + 1]);
                    mma_bf16(acc[mt][n8], a[mt], b1[n8 >> 1][(n8 & 1) * 2],
                             b1[n8 >> 1][(n8 & 1) * 2 + 1]);
                }
            // term a1 with b0
            #pragma unroll
            for (int mt = 0; mt < 4; mt++) {
                int r = wr * 64 + mt * 16 + (lane & 15);
                int c = ks * 2 + (lane >> 4);
                ldsm_x4(a[mt], sA + 16384 + r * 128 + ((uint32_t)((c ^ (r & 7)) & 7) << 4));
            }
            #pragma unroll
            for (int mt = 0; mt < 4; mt++)
                #pragma unroll
                for (int n8 = 0; n8 < 4; n8++)
                    mma_bf16(acc[mt][n8], a[mt], b0[n8 >> 1][(n8 & 1) * 2],
                             b0[n8 >> 1][(n8 & 1) * 2 + 1]);
        }
    }

    float* dst = g_mpart + (size_t)blockIdx.y * (H * D) + (size_t)k0 * 128;
    #pragma unroll
    for (int mt = 0; mt < 4; mt++)
        #pragma unroll
        for (int n8 = 0; n8 < 4; n8++)
            #pragma unroll
            for (int h = 0; h < 2; h++) {
                int r  = wr * 64 + mt * 16 + h * 8 + (lane >> 2);
                int cs = wc * 32 + n8 * 8 + (lane & 3) * 2;
                *(float2*)&dst[(size_t)r * 128 + cs] =
                    make_float2(acc[mt][n8][h * 2], acc[mt][n8][h * 2 + 1]);
            }
}

__global__ __launch_bounds__(256) void mreduce_kernel() {
    int i = blockIdx.x * 256 + threadIdx.x;   // float4 index, 131072 total
    if (i >= H * D / 4) return;
    float4 s = make_float4(0.f, 0.f, 0.f, 0.f);
    #pragma unroll
    for (int p = 0; p < 8; p++) {
        float4 v = ((const float4*)(g_mpart + (size_t)p * H * D))[i];
        s.x += v.x; s.y += v.y; s.z += v.z; s.w += v.w;
    }
    ((float4*)g_MT)[i] = s;
}

// ------------------ stage-1 mma.sync GEMM + argmax + rescore ----------------
// CTA: 128 rows x 128 cols (half segment), K=128. occ 2. Swizzled smem.
static constexpr int LIST_CAP = 1024;
static constexpr int OFF_A    = 0;        // 32768
static constexpr int OFF_B    = 32768;    // 32768
static constexpr int OFF_BS   = 65536;    // 512
static constexpr int OFF_RM4  = 66048;    // 2048
static constexpr int OFF_RMF  = 68096;    // 512
static constexpr int OFF_CNT  = 68608;    // 16
static constexpr int OFF_LIST = 68624;    // 4096
static constexpr int S1_SMEM  = OFF_LIST + LIST_CAP * 4;

__global__ __launch_bounds__(256, 2) void s1mma_kernel(const float* __restrict__ x,
                                                       const float* __restrict__ W1,
                                                       const float* __restrict__ b1) {
    extern __shared__ char sm[];
    const int tid  = threadIdx.x;
    const int lane = tid & 31;
    const int wid  = tid >> 5;
    const int wr   = wid >> 2;
    const int wc   = wid & 3;
    const int tile = blockIdx.x;
    const int seg  = blockIdx.y >> 1;
    const int half = blockIdx.y & 1;
    const int colg = seg * 256 + half * 128;   // global W1 row base for our cols

    float* bs  = (float*)(sm + OFF_BS);
    float (*rm4)[4] = (float(*)[4])(sm + OFF_RM4);
    float* rmf = (float*)(sm + OFF_RMF);
    int* cnt   = (int*)(sm + OFF_CNT);
    uint32_t* list = (uint32_t*)(sm + OFF_LIST);

    if (tid < 128) bs[tid] = b1[colg + tid];
    if (tid == 0) *cnt = 0;

    // loads (swizzled: chunk c of row r goes to c^(r&7))
    const uint4* xb4 = (const uint4*)g_xb + (size_t)tile * 128 * 16;
    #pragma unroll
    for (int i = 0; i < 8; i++) {
        int q = tid + i * 256;
        int r = q >> 4, c = q & 15;
        *(uint4*)(sm + OFF_A + r * 256 + (((c ^ (r & 7))) << 4)) = xb4[r * 16 + c];
    }
    const uint4* wb4 = (const uint4*)g_w1b + (size_t)colg * 16;
    #pragma unroll
    for (int i = 0; i < 8; i++) {
        int q = tid + i * 256;
        int r = q >> 4, c = q & 15;
        *(uint4*)(sm + OFF_B + r * 256 + (((c ^ (r & 7))) << 4)) = wb4[r * 16 + c];
    }
    __syncthreads();

    const uint32_t sA = smem_u32(sm) + OFF_A;
    const uint32_t sB = smem_u32(sm) + OFF_B;

    float acc[4][4][4];
    #pragma unroll
    for (int mt = 0; mt < 4; mt++)
        #pragma unroll
        for (int nt = 0; nt < 4; nt++)
            #pragma unroll
            for (int e = 0; e < 4; e++) acc[mt][nt][e] = 0.f;

    #pragma unroll
    for (int ks = 0; ks < 8; ks++) {
        uint32_t a[4][4], b[2][4];
        #pragma unroll
        for (int mt = 0; mt < 4; mt++) {
            int r = wr * 64 + mt * 16 + (lane & 15);
            int c = ks * 2 + (lane >> 4);
            ldsm_x4(a[mt], sA + r * 256 + ((uint32_t)(c ^ (r & 7)) << 4));
        }
        #pragma unroll
        for (int g = 0; g < 2; g++) {
            int r = wc * 32 + g * 16 + (lane & 7) + ((lane >> 4) << 3);
            int c = ks * 2 + ((lane >> 3) & 1);
            ldsm_x4(b[g], sB + r * 256 + ((uint32_t)(c ^ (r & 7)) << 4));
        }
        #pragma unroll
        for (int mt = 0; mt < 4; mt++)
            #pragma unroll
            for (int n8 = 0; n8 < 4; n8++)
                mma_bf16(acc[mt][n8], a[mt], b[n8 >> 1][(n8 & 1) * 2],
                         b[n8 >> 1][(n8 & 1) * 2 + 1]);
    }

    // pass 1: approx row max over this CTA's 128 cols
    const int q  = lane >> 2;
    const int qt = lane & 3;
    #pragma unroll
    for (int mt = 0; mt < 4; mt++)
        #pragma unroll
        for (int h = 0; h < 2; h++) {
            float vm = -3.402823466e+38f;
            #pragma unroll
            for (int nt = 0; nt < 4; nt++)
                #pragma unroll
                for (int c = 0; c < 2; c++) {
                    float v = acc[mt][nt][h * 2 + c] + bs[wc * 32 + nt * 8 + qt * 2 + c];
                    vm = fmaxf(vm, v);
                }
            vm = fmaxf(vm, __shfl_xor_sync(0xffffffffu, vm, 1));
            vm = fmaxf(vm, __shfl_xor_sync(0xffffffffu, vm, 2));
            if (qt == 0) rm4[wr * 64 + mt * 16 + h * 8 + q][wc] = vm;
        }
    __syncthreads();
    if (tid < 128)
        rmf[tid] = fmaxf(fmaxf(rm4[tid][0], rm4[tid][1]),
                         fmaxf(rm4[tid][2], rm4[tid][3]));
    __syncthreads();

    // pass 2: collect candidates within TAU of half-max
    #pragma unroll
    for (int mt = 0; mt < 4; mt++)
        #pragma unroll
        for (int h = 0; h < 2; h++) {
            int rl = wr * 64 + mt * 16 + h * 8 + q;
            float thr = rmf[rl] - TAU;
            #pragma unroll
            for (int nt = 0; nt < 4; nt++)
                #pragma unroll
                for (int c = 0; c < 2; c++) {
                    int cs = wc * 32 + nt * 8 + qt * 2 + c;
                    float v = acc[mt][nt][h * 2 + c] + bs[cs];
                    if (v >= thr) {
                        int p = atomicAdd(cnt, 1);
                        if (p < LIST_CAP) list[p] = ((uint32_t)rl << 8) | (uint32_t)cs;
                    }
                }
        }
    __syncthreads();

    // exact fp32 rescore, merge across halves via global atomicMax key
    int n = *cnt;
    if (n > LIST_CAP) n = LIST_CAP;
    for (int i = wid; i < n; i += 8) {
        uint32_t e = list[i];
        int rl = e >> 8, cs = e & 255;
        const float4* xr = (const float4*)(x  + (size_t)(tile * 128 + rl) * 128);
        const float4* wv = (const float4*)(W1 + (size_t)(colg + cs) * 128);
        float4 xa = __ldg(&xr[lane]);
        float4 wa = __ldg(&wv[lane]);
        float s = xa.x * wa.x + xa.y * wa.y + xa.z * wa.z + xa.w * wa.w;
        #pragma unroll
        for (int off = 16; off > 0; off >>= 1)
            s += __shfl_xor_sync(0xffffffffu, s, off);
        if (lane == 0) {
            float val = s + bs[cs];
            int gcol = half * 128 + cs;
            unsigned long long key =
                ((unsigned long long)ford(val) << 32) | (uint32_t)(255 - gcol);
            atomicMax(&g_kb[(size_t)(tile * 128 + rl) * NSEG + seg], key);
        }
    }
}

// --------------------------------- gather ---------------------------------
__global__ __launch_bounds__(128) void gather_kernel(float* __restrict__ out) {
    const int rowbase = blockIdx.x * 16;
    const int t = threadIdx.x;
    __shared__ int sidx[16][16];
    #pragma unroll
    for (int qq = t; qq < 256; qq += 128) {
        unsigned long long key = g_kb[(size_t)(rowbase + (qq >> 4)) * NSEG + (qq & 15)];
        sidx[qq >> 4][qq & 15] = 255 - (int)(key & 0xFFu);
    }
    __syncthreads();

    const float cv = g_c[t];
    float acc[16];
    #pragma unroll
    for (int r = 0; r < 16; r++) acc[r] = cv;

    #pragma unroll
    for (int s = 0; s < NSEG; s++) {
        #pragma unroll
        for (int r = 0; r < 16; r++) {
            int col = (s << 8) + sidx[r][s];
            acc[r] += g_MT[(size_t)col * D + t];
        }
    }
    #pragma unroll
    for (int r = 0; r < 16; r++)
        out[(size_t)(rowbase + r) * D + t] = acc[r];
}

// ------------------------------- launcher ----------------------------------
extern "C" void kernel_launch(void* const* d_in, const int* in_sizes, int n_in,
                              void* d_out, int out_size) {
    const float* x  = (const float*)d_in[0];
    const float* W1 = (const float*)d_in[1];
    const float* b1 = (const float*)d_in[2];
    const float* W2 = (const float*)d_in[3];
    const float* b2 = (const float*)d_in[4];
    const float* W3 = (const float*)d_in[5];
    const float* b3 = (const float*)d_in[6];
    float* out = (float*)d_out;
    const int B = in_sizes[0] / D;   // 32768

    void *p_xb = nullptr, *p_w1b = nullptr;
    cudaGetSymbolAddress(&p_xb,  g_xb);
    cudaGetSymbolAddress(&p_w1b, g_w1b);

    cudaFuncSetAttribute(s1mma_kernel,
                         cudaFuncAttributeMaxDynamicSharedMemorySize, S1_SMEM);
    cudaFuncSetAttribute(mm2_kernel,
                         cudaFuncAttributeMaxDynamicSharedMemorySize, MM_SMEM);

    convertb_kernel<<<(B * D / 8 + 255) / 256, 256>>>(x,  (__nv_bfloat16*)p_xb,  B * D / 8);
    convertb_kernel<<<(H * D / 8 + 255) / 256, 256>>>(W1, (__nv_bfloat16*)p_w1b, H * D / 8);
    w3split_kernel<<<(H * D / 2 + 255) / 256, 256>>>(W3);
    w2split_kernel<<<dim3(H / 32, H / 32), dim3(32, 8)>>>(W2);

    c_kernel<<<D, 256>>>(W3, b2, b3);
    mm2_kernel<<<dim3(32, 8), 256, MM_SMEM>>>();
    mreduce_kernel<<<(H * D / 4 + 255) / 256, 256>>>();

    kbinit_kernel<<<(BMAX * NSEG + 255) / 256, 256>>>();
    s1mma_kernel<<<dim3(B / 128, NSEG * 2), 256, S1_SMEM>>>(x, W1, b1);
    gather_kernel<<<B / 16, 128>>>(out);
}

// round 6
// speedup vs baseline: 2.9139x; 1.1751x over previous
#include <cuda_runtime.h>
#include <cuda_bf16.h>
#include <cstdint>
#include <cstddef>

// ---------------------------------------------------------------------------
// Sbox16: out = c + sum_seg M[:, seg*256 + argmax_seg(x@W1^T + b1)]
//   M = W3@W2 (128x4096), c = W3@b2 + b3
// R6: s1 CTAs cover full 256-col segments (64 rows, occ 2). Rows whose approx
//     top-1 margin exceeds tau are written directly (provably exact); only
//     ambiguous rows (~17%) get exact fp32 rescore. No global key atomics.
// ---------------------------------------------------------------------------

static constexpr int BMAX = 32768;
static constexpr int D    = 128;
static constexpr int H    = 4096;
static constexpr int NSEG = 16;
static constexpr float TAU = 0.13f;

__device__ __nv_bfloat16 g_xb [BMAX * D];            // bf16(x) row-major
__device__ __nv_bfloat16 g_w1b[H * D];               // bf16(W1) row-major
__device__ __nv_bfloat16 g_w2t[2 * (size_t)H * H];   // [term][k][j] = W2[j][k] split
__device__ __nv_bfloat16 g_w3b[2 * H * D];           // [term][i][j] split of W3
__device__ float g_mpart[8 * H * D];                 // [jsplit][k][i]
__device__ float g_MT [H * D];                       // [k][i]
__device__ float g_c  [D];
__device__ int   g_idx[BMAX * NSEG];

// ------------------------------- ptx helpers -------------------------------
__device__ __forceinline__ uint32_t smem_u32(const void* p) {
    uint32_t a;
    asm("{ .reg .u64 t; cvta.to.shared.u64 t, %1; cvt.u32.u64 %0, t; }" : "=r"(a) : "l"(p));
    return a;
}
__device__ __forceinline__ void ldsm_x4(uint32_t* r, uint32_t addr) {
    asm volatile("ldmatrix.sync.aligned.m8n8.x4.shared.b16 {%0,%1,%2,%3}, [%4];"
                 : "=r"(r[0]), "=r"(r[1]), "=r"(r[2]), "=r"(r[3]) : "r"(addr));
}
__device__ __forceinline__ void mma_bf16(float* d, const uint32_t* a,
                                         uint32_t b0, uint32_t b1) {
    asm volatile("mma.sync.aligned.m16n8k16.row.col.f32.bf16.bf16.f32 "
                 "{%0,%1,%2,%3}, {%4,%5,%6,%7}, {%8,%9}, {%0,%1,%2,%3};"
                 : "+f"(d[0]), "+f"(d[1]), "+f"(d[2]), "+f"(d[3])
                 : "r"(a[0]), "r"(a[1]), "r"(a[2]), "r"(a[3]), "r"(b0), "r"(b1));
}
__device__ __forceinline__ uint32_t ford(float f) {
    uint32_t u = __float_as_uint(f);
    return (u & 0x80000000u) ? ~u : (u | 0x80000000u);
}

// ------------------------------ prepasses ----------------------------------
__global__ __launch_bounds__(256) void convertb_kernel(const float* __restrict__ src,
                                                       __nv_bfloat16* __restrict__ dst,
                                                       int n8) {
    int i = blockIdx.x * 256 + threadIdx.x;
    if (i >= n8) return;
    const float4* s4 = (const float4*)src;
    float4 a = s4[i * 2], b = s4[i * 2 + 1];
    __nv_bfloat162 p0 = __float22bfloat162_rn(make_float2(a.x, a.y));
    __nv_bfloat162 p1 = __float22bfloat162_rn(make_float2(a.z, a.w));
    __nv_bfloat162 p2 = __float22bfloat162_rn(make_float2(b.x, b.y));
    __nv_bfloat162 p3 = __float22bfloat162_rn(make_float2(b.z, b.w));
    uint4 o;
    o.x = *(uint32_t*)&p0; o.y = *(uint32_t*)&p1;
    o.z = *(uint32_t*)&p2; o.w = *(uint32_t*)&p3;
    ((uint4*)dst)[i] = o;
}

__global__ __launch_bounds__(256) void w3split_kernel(const float* __restrict__ W3) {
    int i = blockIdx.x * 256 + threadIdx.x;
    if (i >= H * D / 2) return;
    float2 v = ((const float2*)W3)[i];
    __nv_bfloat16 a0 = __float2bfloat16(v.x);
    __nv_bfloat16 b0 = __float2bfloat16(v.x - __bfloat162float(a0));
    __nv_bfloat16 a1 = __float2bfloat16(v.y);
    __nv_bfloat16 b1 = __float2bfloat16(v.y - __bfloat162float(a1));
    __nv_bfloat162 pa = {a0, a1}, pb = {b0, b1};
    ((__nv_bfloat162*)g_w3b)[i] = pa;
    ((__nv_bfloat162*)g_w3b)[H * D / 2 + i] = pb;
}

__global__ void w2split_kernel(const float* __restrict__ W2) {
    __shared__ float tile[32][33];
    int k0 = blockIdx.x * 32;
    int j0 = blockIdx.y * 32;
    int tx = threadIdx.x, ty = threadIdx.y;
    #pragma unroll
    for (int i = ty; i < 32; i += 8)
        tile[i][tx] = W2[(size_t)(j0 + i) * H + k0 + tx];
    __syncthreads();
    if (tx < 16) {
        #pragma unroll
        for (int i = ty; i < 32; i += 8) {
            float v0 = tile[2 * tx][i];
            float v1 = tile[2 * tx + 1][i];
            __nv_bfloat16 a0 = __float2bfloat16(v0);
            __nv_bfloat16 b0 = __float2bfloat16(v0 - __bfloat162float(a0));
            __nv_bfloat16 a1 = __float2bfloat16(v1);
            __nv_bfloat16 b1 = __float2bfloat16(v1 - __bfloat162float(a1));
            __nv_bfloat162 pa = {a0, a1}, pb = {b0, b1};
            size_t off = (size_t)(k0 + i) * H + j0 + 2 * tx;
            *(__nv_bfloat162*)(g_w2t + off) = pa;
            *(__nv_bfloat162*)(g_w2t + (size_t)H * H + off) = pb;
        }
    }
}

// ---------------------------------- c ------------------------------------
__global__ void c_kernel(const float* __restrict__ W3,
                         const float* __restrict__ b2,
                         const float* __restrict__ b3) {
    const int i = blockIdx.x;
    float s = 0.f;
    for (int j = threadIdx.x; j < H; j += 256)
        s += W3[(size_t)i * H + j] * b2[j];
    __shared__ float red[256];
    red[threadIdx.x] = s;
    __syncthreads();
    for (int o = 128; o > 0; o >>= 1) {
        if (threadIdx.x < o) red[threadIdx.x] += red[threadIdx.x + o];
        __syncthreads();
    }
    if (threadIdx.x == 0) g_c[i] = red[0] + b3[i];
}

// ----------------- M via mma.sync: MT[k][i] = sum_j W2[j][k]W3[i][j] --------
static constexpr int MM_SMEM = 65536;

__global__ __launch_bounds__(256, 2) void mm2_kernel() {
    extern __shared__ char sm[];
    const int tid  = threadIdx.x;
    const int lane = tid & 31;
    const int wid  = tid >> 5;
    const int wr   = wid >> 2;
    const int wc   = wid & 3;
    const int k0   = blockIdx.x * 128;
    const int j0   = blockIdx.y * 512;

    const uint32_t sA = smem_u32(sm);
    const uint32_t sB = sA + 32768;

    float acc[4][4][4];
    #pragma unroll
    for (int mt = 0; mt < 4; mt++)
        #pragma unroll
        for (int nt = 0; nt < 4; nt++)
            #pragma unroll
            for (int e = 0; e < 4; e++) acc[mt][nt][e] = 0.f;

    for (int jc = 0; jc < 8; jc++) {
        __syncthreads();
        #pragma unroll
        for (int t = 0; t < 2; t++) {
            const __nv_bfloat16* srcA = g_w2t + (size_t)t * H * H
                                      + (size_t)k0 * H + j0 + jc * 64;
            #pragma unroll
            for (int i = 0; i < 4; i++) {
                int q = tid + i * 256;
                int r = q >> 3, c = q & 7;
                *(uint4*)(sm + t * 16384 + r * 128 + (((c ^ (r & 7)) & 7) << 4)) =
                    *(const uint4*)(srcA + (size_t)r * H + c * 8);
            }
        }
        #pragma unroll
        for (int t = 0; t < 2; t++) {
            const __nv_bfloat16* srcB = g_w3b + (size_t)t * H * D
                                      + j0 + jc * 64;
            #pragma unroll
            for (int i = 0; i < 4; i++) {
                int q = tid + i * 256;
                int r = q >> 3, c = q & 7;
                *(uint4*)(sm + 32768 + t * 16384 + r * 128 + (((c ^ (r & 7)) & 7) << 4)) =
                    *(const uint4*)(srcB + (size_t)r * H + c * 8);
            }
        }
        __syncthreads();

        #pragma unroll
        for (int ks = 0; ks < 4; ks++) {
            uint32_t b0[2][4], b1[2][4], a[4][4];
            #pragma unroll
            for (int g = 0; g < 2; g++) {
                int r = wc * 32 + g * 16 + (lane & 7) + ((lane >> 4) << 3);
                int c = ks * 2 + ((lane >> 3) & 1);
                uint32_t sw = (uint32_t)((c ^ (r & 7)) & 7) << 4;
                ldsm_x4(b0[g], sB + r * 128 + sw);
                ldsm_x4(b1[g], sB + 16384 + r * 128 + sw);
            }
            #pragma unroll
            for (int mt = 0; mt < 4; mt++) {
                int r = wr * 64 + mt * 16 + (lane & 15);
                int c = ks * 2 + (lane >> 4);
                ldsm_x4(a[mt], sA + r * 128 + ((uint32_t)((c ^ (r & 7)) & 7) << 4));
            }
            #pragma unroll
            for (int mt = 0; mt < 4; mt++)
                #pragma unroll
                for (int n8 = 0; n8 < 4; n8++) {
                    mma_bf16(acc[mt][n8], a[mt], b0[n8 >> 1][(n8 & 1) * 2],
                             b0[n8 >> 1][(n8 & 1) * 2 + 1]);
                    mma_bf16(acc[mt][n8], a[mt], b1[n8 >> 1][(n8 & 1) * 2],
                             b1[n8 >> 1][(n8 & 1) * 2 + 1]);
                }
            #pragma unroll
            for (int mt = 0; mt < 4; mt++) {
                int r = wr * 64 + mt * 16 + (lane & 15);
                int c = ks * 2 + (lane >> 4);
                ldsm_x4(a[mt], sA + 16384 + r * 128 + ((uint32_t)((c ^ (r & 7)) & 7) << 4));
            }
            #pragma unroll
            for (int mt = 0; mt < 4; mt++)
                #pragma unroll
                for (int n8 = 0; n8 < 4; n8++)
                    mma_bf16(acc[mt][n8], a[mt], b0[n8 >> 1][(n8 & 1) * 2],
                             b0[n8 >> 1][(n8 & 1) * 2 + 1]);
        }
    }

    float* dst = g_mpart + (size_t)blockIdx.y * (H * D) + (size_t)k0 * 128;
    #pragma unroll
    for (int mt = 0; mt < 4; mt++)
        #pragma unroll
        for (int n8 = 0; n8 < 4; n8++)
            #pragma unroll
            for (int h = 0; h < 2; h++) {
                int r  = wr * 64 + mt * 16 + h * 8 + (lane >> 2);
                int cs = wc * 32 + n8 * 8 + (lane & 3) * 2;
                *(float2*)&dst[(size_t)r * 128 + cs] =
                    make_float2(acc[mt][n8][h * 2], acc[mt][n8][h * 2 + 1]);
            }
}

__global__ __launch_bounds__(256) void mreduce_kernel() {
    int i = blockIdx.x * 256 + threadIdx.x;
    if (i >= H * D / 4) return;
    float4 s = make_float4(0.f, 0.f, 0.f, 0.f);
    #pragma unroll
    for (int p = 0; p < 8; p++) {
        float4 v = ((const float4*)(g_mpart + (size_t)p * H * D))[i];
        s.x += v.x; s.y += v.y; s.z += v.z; s.w += v.w;
    }
    ((float4*)g_MT)[i] = s;
}

// ------------------ stage-1 mma.sync GEMM + argmax + rescore ----------------
// CTA: 64 rows x 256 cols (FULL segment), K=128, 256 thr (warps 2r x 4c),
// warp tile 32x64. occ 2. Unambiguous rows written directly; ambiguous
// rows (~17%) exact-rescored with smem key merge.
static constexpr int LIST_CAP = 512;
static constexpr int OFF_A    = 0;        // 64x256B  = 16384
static constexpr int OFF_B    = 16384;    // 256x256B = 65536
static constexpr int OFF_BS   = 81920;    // 1024
static constexpr int OFF_RM4  = 82944;    // 64*4*4 = 1024
static constexpr int OFF_RMF  = 83968;    // 256
static constexpr int OFF_RKA  = 84224;    // u64[64] approx keys
static constexpr int OFF_RKE  = 84736;    // u64[64] exact keys
static constexpr int OFF_RC   = 85248;    // int[64] cand counts
static constexpr int OFF_CNT  = 85504;    // 16
static constexpr int OFF_LIST = 85520;    // 2048
static constexpr int S1_SMEM  = OFF_LIST + LIST_CAP * 4;   // 87568

__global__ __launch_bounds__(256, 2) void s1mma_kernel(const float* __restrict__ x,
                                                       const float* __restrict__ W1,
                                                       const float* __restrict__ b1) {
    extern __shared__ char sm[];
    const int tid  = threadIdx.x;
    const int lane = tid & 31;
    const int wid  = tid >> 5;
    const int wr   = wid >> 2;      // 0..1 (32 rows each)
    const int wc   = wid & 3;       // 0..3 (64 cols each)
    const int tile = blockIdx.x;    // 64-row tile
    const int seg  = blockIdx.y;

    float* bs  = (float*)(sm + OFF_BS);
    float (*rm4)[4] = (float(*)[4])(sm + OFF_RM4);
    float* rmf = (float*)(sm + OFF_RMF);
    unsigned long long* rka = (unsigned long long*)(sm + OFF_RKA);
    unsigned long long* rke = (unsigned long long*)(sm + OFF_RKE);
    int* rc   = (int*)(sm + OFF_RC);
    int* cnt  = (int*)(sm + OFF_CNT);
    uint32_t* list = (uint32_t*)(sm + OFF_LIST);

    bs[tid] = b1[seg * 256 + tid];
    if (tid < 64) { rka[tid] = 0ull; rke[tid] = 0ull; rc[tid] = 0; }
    if (tid == 0) *cnt = 0;

    // A: 64x128 bf16 (row 256B, swizzled 16B chunks)
    const uint4* xb4 = (const uint4*)g_xb + (size_t)tile * 64 * 16;
    #pragma unroll
    for (int i = 0; i < 4; i++) {
        int q = tid + i * 256;
        int r = q >> 4, c = q & 15;
        *(uint4*)(sm + OFF_A + r * 256 + ((c ^ (r & 7)) << 4)) = xb4[r * 16 + c];
    }
    // B: 256x128 bf16
    const uint4* wb4 = (const uint4*)g_w1b + (size_t)seg * 256 * 16;
    #pragma unroll
    for (int i = 0; i < 16; i++) {
        int q = tid + i * 256;
        int r = q >> 4, c = q & 15;
        *(uint4*)(sm + OFF_B + r * 256 + ((c ^ (r & 7)) << 4)) = wb4[r * 16 + c];
    }
    __syncthreads();

    const uint32_t sA = smem_u32(sm) + OFF_A;
    const uint32_t sB = smem_u32(sm) + OFF_B;

    float acc[2][8][4];
    #pragma unroll
    for (int mt = 0; mt < 2; mt++)
        #pragma unroll
        for (int nt = 0; nt < 8; nt++)
            #pragma unroll
            for (int e = 0; e < 4; e++) acc[mt][nt][e] = 0.f;

    #pragma unroll
    for (int ks = 0; ks < 8; ks++) {
        uint32_t a[2][4], b[4][4];
        #pragma unroll
        for (int mt = 0; mt < 2; mt++) {
            int r = wr * 32 + mt * 16 + (lane & 15);
            int c = ks * 2 + (lane >> 4);
            ldsm_x4(a[mt], sA + r * 256 + ((uint32_t)(c ^ (r & 7)) << 4));
        }
        #pragma unroll
        for (int g = 0; g < 4; g++) {
            int r = wc * 64 + g * 16 + (lane & 7) + ((lane >> 4) << 3);
            int c = ks * 2 + ((lane >> 3) & 1);
            ldsm_x4(b[g], sB + r * 256 + ((uint32_t)(c ^ (r & 7)) << 4));
        }
        #pragma unroll
        for (int mt = 0; mt < 2; mt++)
            #pragma unroll
            for (int n8 = 0; n8 < 8; n8++)
                mma_bf16(acc[mt][n8], a[mt], b[n8 >> 1][(n8 & 1) * 2],
                         b[n8 >> 1][(n8 & 1) * 2 + 1]);
    }

    // pass 1: approx row max over warp's 64 cols -> rm4, then full 256 -> rmf
    const int q  = lane >> 2;
    const int qt = lane & 3;
    #pragma unroll
    for (int mt = 0; mt < 2; mt++)
        #pragma unroll
        for (int h = 0; h < 2; h++) {
            float vm = -3.402823466e+38f;
            #pragma unroll
            for (int nt = 0; nt < 8; nt++)
                #pragma unroll
                for (int c = 0; c < 2; c++) {
                    float v = acc[mt][nt][h * 2 + c] + bs[wc * 64 + nt * 8 + qt * 2 + c];
                    vm = fmaxf(vm, v);
                }
            vm = fmaxf(vm, __shfl_xor_sync(0xffffffffu, vm, 1));
            vm = fmaxf(vm, __shfl_xor_sync(0xffffffffu, vm, 2));
            if (qt == 0) rm4[wr * 32 + mt * 16 + h * 8 + q][wc] = vm;
        }
    __syncthreads();
    if (tid < 64)
        rmf[tid] = fmaxf(fmaxf(rm4[tid][0], rm4[tid][1]),
                         fmaxf(rm4[tid][2], rm4[tid][3]));
    __syncthreads();

    // pass 2: candidates within TAU; per-row count + approx best key + list
    #pragma unroll
    for (int mt = 0; mt < 2; mt++)
        #pragma unroll
        for (int h = 0; h < 2; h++) {
            int rl = wr * 32 + mt * 16 + h * 8 + q;
            float thr = rmf[rl] - TAU;
            #pragma unroll
            for (int nt = 0; nt < 8; nt++)
                #pragma unroll
                for (int c = 0; c < 2; c++) {
                    int cs = wc * 64 + nt * 8 + qt * 2 + c;
                    float v = acc[mt][nt][h * 2 + c] + bs[cs];
                    if (v >= thr) {
                        atomicAdd(&rc[rl], 1);
                        unsigned long long key =
                            ((unsigned long long)ford(v) << 32) | (uint32_t)(255 - cs);
                        atomicMax(&rka[rl], key);
                        int p = atomicAdd(cnt, 1);
                        if (p < LIST_CAP) list[p] = ((uint32_t)rl << 8) | (uint32_t)cs;
                    }
                }
        }
    __syncthreads();

    // direct write for unambiguous rows (margin > TAU: provably exact)
    if (tid < 64 && rc[tid] == 1) {
        int col = 255 - (int)(rka[tid] & 0xFFu);
        g_idx[(size_t)(tile * 64 + tid) * NSEG + seg] = col;
    }

    // exact rescore of ambiguous rows only
    int n = *cnt;
    if (n > LIST_CAP) n = LIST_CAP;
    for (int i = wid; i < n; i += 8) {
        uint32_t e = list[i];
        int rl = e >> 8, cs = e & 255;
        if (rc[rl] < 2) continue;
        const float4* xr = (const float4*)(x  + (size_t)(tile * 64 + rl) * 128);
        const float4* wv = (const float4*)(W1 + (size_t)(seg * 256 + cs) * 128);
        float4 xa = __ldg(&xr[lane]);
        float4 wa = __ldg(&wv[lane]);
        float s = xa.x * wa.x + xa.y * wa.y + xa.z * wa.z + xa.w * wa.w;
        #pragma unroll
        for (int off = 16; off > 0; off >>= 1)
            s += __shfl_xor_sync(0xffffffffu, s, off);
        if (lane == 0) {
            float val = s + bs[cs];
            unsigned long long key =
                ((unsigned long long)ford(val) << 32) | (uint32_t)(255 - cs);
            atomicMax(&rke[rl], key);
        }
    }
    __syncthreads();
    if (tid < 64 && rc[tid] > 1) {
        int col = 255 - (int)(rke[tid] & 0xFFu);
        g_idx[(size_t)(tile * 64 + tid) * NSEG + seg] = col;
    }
}

// --------------------------------- gather ---------------------------------
__global__ __launch_bounds__(128) void gather_kernel(float* __restrict__ out) {
    const int rowbase = blockIdx.x * 16;
    const int t = threadIdx.x;
    __shared__ int sidx[16][16];
    #pragma unroll
    for (int qq = t; qq < 256; qq += 128)
        sidx[qq >> 4][qq & 15] = g_idx[(size_t)(rowbase + (qq >> 4)) * NSEG + (qq & 15)];
    __syncthreads();

    const float cv = g_c[t];
    float acc[16];
    #pragma unroll
    for (int r = 0; r < 16; r++) acc[r] = cv;

    #pragma unroll
    for (int s = 0; s < NSEG; s++) {
        #pragma unroll
        for (int r = 0; r < 16; r++) {
            int col = (s << 8) + sidx[r][s];
            acc[r] += g_MT[(size_t)col * D + t];
        }
    }
    #pragma unroll
    for (int r = 0; r < 16; r++)
        out[(size_t)(rowbase + r) * D + t] = acc[r];
}

// ------------------------------- launcher ----------------------------------
extern "C" void kernel_launch(void* const* d_in, const int* in_sizes, int n_in,
                              void* d_out, int out_size) {
    const float* x  = (const float*)d_in[0];
    const float* W1 = (const float*)d_in[1];
    const float* b1 = (const float*)d_in[2];
    const float* W2 = (const float*)d_in[3];
    const float* b2 = (const float*)d_in[4];
    const float* W3 = (const float*)d_in[5];
    const float* b3 = (const float*)d_in[6];
    float* out = (float*)d_out;
    const int B = in_sizes[0] / D;   // 32768

    void *p_xb = nullptr, *p_w1b = nullptr;
    cudaGetSymbolAddress(&p_xb,  g_xb);
    cudaGetSymbolAddress(&p_w1b, g_w1b);

    cudaFuncSetAttribute(s1mma_kernel,
                         cudaFuncAttributeMaxDynamicSharedMemorySize, S1_SMEM);
    cudaFuncSetAttribute(mm2_kernel,
                         cudaFuncAttributeMaxDynamicSharedMemorySize, MM_SMEM);

    convertb_kernel<<<(B * D / 8 + 255) / 256, 256>>>(x,  (__nv_bfloat16*)p_xb,  B * D / 8);
    convertb_kernel<<<(H * D / 8 + 255) / 256, 256>>>(W1, (__nv_bfloat16*)p_w1b, H * D / 8);
    w3split_kernel<<<(H * D / 2 + 255) / 256, 256>>>(W3);
    w2split_kernel<<<dim3(H / 32, H / 32), dim3(32, 8)>>>(W2);

    c_kernel<<<D, 256>>>(W3, b2, b3);
    mm2_kernel<<<dim3(32, 8), 256, MM_SMEM>>>();
    mreduce_kernel<<<(H * D / 4 + 255) / 256, 256>>>();

    s1mma_kernel<<<dim3(B / 64, NSEG), 256, S1_SMEM>>>(x, W1, b1);
    gather_kernel<<<B / 16, 128>>>(out);
}

// round 8
// speedup vs baseline: 3.1897x; 1.0947x over previous
#include <cuda_runtime.h>
#include <cuda_bf16.h>
#include <cstdint>
#include <cstddef>

// ---------------------------------------------------------------------------
// Sbox16: out = c + sum_seg M[:, seg*256 + argmax_seg(x@W1^T + b1)]
//   M = W3@W2 (128x4096), c = W3@b2 + b3
// R8: R7 (persistent s1 CTAs, cp.async double-buffered A, B loaded once)
//     with the w2split alignment bug fixed (row stride 65 -> 68 floats).
// ---------------------------------------------------------------------------

static constexpr int BMAX = 32768;
static constexpr int D    = 128;
static constexpr int H    = 4096;
static constexpr int NSEG = 16;
static constexpr float TAU = 0.13f;
static constexpr int NTILE = BMAX / 64;      // 512 row tiles
static constexpr int SGRID = 37;             // CTAs per segment (2 waves @ occ2)

__device__ __nv_bfloat16 g_xb [BMAX * D];
__device__ __nv_bfloat16 g_w1b[H * D];
__device__ __nv_bfloat16 g_w2t[2 * (size_t)H * H];
__device__ __nv_bfloat16 g_w3b[2 * H * D];
__device__ float g_mpart[8 * H * D];
__device__ float g_MT [H * D];
__device__ float g_c  [D];
__device__ int   g_idx[BMAX * NSEG];

// ------------------------------- ptx helpers -------------------------------
__device__ __forceinline__ uint32_t smem_u32(const void* p) {
    uint32_t a;
    asm("{ .reg .u64 t; cvta.to.shared.u64 t, %1; cvt.u32.u64 %0, t; }" : "=r"(a) : "l"(p));
    return a;
}
__device__ __forceinline__ void ldsm_x4(uint32_t* r, uint32_t addr) {
    asm volatile("ldmatrix.sync.aligned.m8n8.x4.shared.b16 {%0,%1,%2,%3}, [%4];"
                 : "=r"(r[0]), "=r"(r[1]), "=r"(r[2]), "=r"(r[3]) : "r"(addr));
}
__device__ __forceinline__ void mma_bf16(float* d, const uint32_t* a,
                                         uint32_t b0, uint32_t b1) {
    asm volatile("mma.sync.aligned.m16n8k16.row.col.f32.bf16.bf16.f32 "
                 "{%0,%1,%2,%3}, {%4,%5,%6,%7}, {%8,%9}, {%0,%1,%2,%3};"
                 : "+f"(d[0]), "+f"(d[1]), "+f"(d[2]), "+f"(d[3])
                 : "r"(a[0]), "r"(a[1]), "r"(a[2]), "r"(a[3]), "r"(b0), "r"(b1));
}
__device__ __forceinline__ uint32_t ford(float f) {
    uint32_t u = __float_as_uint(f);
    return (u & 0x80000000u) ? ~u : (u | 0x80000000u);
}
__device__ __forceinline__ void cpasync16(uint32_t dst, const void* src) {
    asm volatile("cp.async.cg.shared.global [%0], [%1], 16;" :: "r"(dst), "l"(src));
}
#define CP_COMMIT() asm volatile("cp.async.commit_group;" ::: "memory")
#define CP_WAIT1()  asm volatile("cp.async.wait_group 1;" ::: "memory")

// ------------------------------ prepasses ----------------------------------
__global__ __launch_bounds__(256) void convertb_kernel(const float* __restrict__ src,
                                                       __nv_bfloat16* __restrict__ dst,
                                                       int n8) {
    int i = blockIdx.x * 256 + threadIdx.x;
    if (i >= n8) return;
    const float4* s4 = (const float4*)src;
    float4 a = s4[i * 2], b = s4[i * 2 + 1];
    __nv_bfloat162 p0 = __float22bfloat162_rn(make_float2(a.x, a.y));
    __nv_bfloat162 p1 = __float22bfloat162_rn(make_float2(a.z, a.w));
    __nv_bfloat162 p2 = __float22bfloat162_rn(make_float2(b.x, b.y));
    __nv_bfloat162 p3 = __float22bfloat162_rn(make_float2(b.z, b.w));
    uint4 o;
    o.x = *(uint32_t*)&p0; o.y = *(uint32_t*)&p1;
    o.z = *(uint32_t*)&p2; o.w = *(uint32_t*)&p3;
    ((uint4*)dst)[i] = o;
}

__global__ __launch_bounds__(256) void w3split_kernel(const float* __restrict__ W3) {
    int i = blockIdx.x * 256 + threadIdx.x;
    if (i >= H * D / 2) return;
    float2 v = ((const float2*)W3)[i];
    __nv_bfloat16 a0 = __float2bfloat16(v.x);
    __nv_bfloat16 b0 = __float2bfloat16(v.x - __bfloat162float(a0));
    __nv_bfloat16 a1 = __float2bfloat16(v.y);
    __nv_bfloat16 b1 = __float2bfloat16(v.y - __bfloat162float(a1));
    __nv_bfloat162 pa = {a0, a1}, pb = {b0, b1};
    ((__nv_bfloat162*)g_w3b)[i] = pa;
    ((__nv_bfloat162*)g_w3b)[H * D / 2 + i] = pb;
}

// W2 transpose + 2-term split, 64x64 fp32 tiles, stride 68 floats (16B-aligned).
__global__ __launch_bounds__(256) void w2split_kernel(const float* __restrict__ W2) {
    __shared__ float tile[64][68];
    const int tid = threadIdx.x;
    const int j0 = blockIdx.x * 64;   // source row block
    const int k0 = blockIdx.y * 64;   // source col block
    #pragma unroll
    for (int p = 0; p < 4; p++) {
        int q = tid + p * 256;
        int r = q >> 4, c = (q & 15) * 4;
        *(float4*)&tile[r][c] = *(const float4*)&W2[(size_t)(j0 + r) * H + k0 + c];
    }
    __syncthreads();
    #pragma unroll
    for (int p = 0; p < 2; p++) {
        int q = tid + p * 256;
        int k = q >> 3, cs = (q & 7) * 8;   // out row k, 8 j values
        __nv_bfloat16 ma[8], mb[8];
        #pragma unroll
        for (int e = 0; e < 8; e++) {
            float v = tile[cs + e][k];
            ma[e] = __float2bfloat16(v);
            mb[e] = __float2bfloat16(v - __bfloat162float(ma[e]));
        }
        size_t off = (size_t)(k0 + k) * H + j0 + cs;
        *(uint4*)(g_w2t + off) = *(uint4*)ma;
        *(uint4*)(g_w2t + (size_t)H * H + off) = *(uint4*)mb;
    }
}

// ---------------------------------- c ------------------------------------
__global__ void c_kernel(const float* __restrict__ W3,
                         const float* __restrict__ b2,
                         const float* __restrict__ b3) {
    const int i = blockIdx.x;
    float s = 0.f;
    for (int j = threadIdx.x; j < H; j += 256)
        s += W3[(size_t)i * H + j] * b2[j];
    __shared__ float red[256];
    red[threadIdx.x] = s;
    __syncthreads();
    for (int o = 128; o > 0; o >>= 1) {
        if (threadIdx.x < o) red[threadIdx.x] += red[threadIdx.x + o];
        __syncthreads();
    }
    if (threadIdx.x == 0) g_c[i] = red[0] + b3[i];
}

// ----------------- M via mma.sync: MT[k][i] = sum_j W2[j][k]W3[i][j] --------
static constexpr int MM_SMEM = 65536;

__global__ __launch_bounds__(256, 2) void mm2_kernel() {
    extern __shared__ char sm[];
    const int tid  = threadIdx.x;
    const int lane = tid & 31;
    const int wid  = tid >> 5;
    const int wr   = wid >> 2;
    const int wc   = wid & 3;
    const int k0   = blockIdx.x * 128;
    const int j0   = blockIdx.y * 512;

    const uint32_t sA = smem_u32(sm);
    const uint32_t sB = sA + 32768;

    float acc[4][4][4];
    #pragma unroll
    for (int mt = 0; mt < 4; mt++)
        #pragma unroll
        for (int nt = 0; nt < 4; nt++)
            #pragma unroll
            for (int e = 0; e < 4; e++) acc[mt][nt][e] = 0.f;

    for (int jc = 0; jc < 8; jc++) {
        __syncthreads();
        #pragma unroll
        for (int t = 0; t < 2; t++) {
            const __nv_bfloat16* srcA = g_w2t + (size_t)t * H * H
                                      + (size_t)k0 * H + j0 + jc * 64;
            #pragma unroll
            for (int i = 0; i < 4; i++) {
                int q = tid + i * 256;
                int r = q >> 3, c = q & 7;
                *(uint4*)(sm + t * 16384 + r * 128 + (((c ^ (r & 7)) & 7) << 4)) =
                    *(const uint4*)(srcA + (size_t)r * H + c * 8);
            }
        }
        #pragma unroll
        for (int t = 0; t < 2; t++) {
            const __nv_bfloat16* srcB = g_w3b + (size_t)t * H * D
                                      + j0 + jc * 64;
            #pragma unroll
            for (int i = 0; i < 4; i++) {
                int q = tid + i * 256;
                int r = q >> 3, c = q & 7;
                *(uint4*)(sm + 32768 + t * 16384 + r * 128 + (((c ^ (r & 7)) & 7) << 4)) =
                    *(const uint4*)(srcB + (size_t)r * H + c * 8);
            }
        }
        __syncthreads();

        #pragma unroll
        for (int ks = 0; ks < 4; ks++) {
            uint32_t b0[2][4], b1[2][4], a[4][4];
            #pragma unroll
            for (int g = 0; g < 2; g++) {
                int r = wc * 32 + g * 16 + (lane & 7) + ((lane >> 4) << 3);
                int c = ks * 2 + ((lane >> 3) & 1);
                uint32_t sw = (uint32_t)((c ^ (r & 7)) & 7) << 4;
                ldsm_x4(b0[g], sB + r * 128 + sw);
                ldsm_x4(b1[g], sB + 16384 + r * 128 + sw);
            }
            #pragma unroll
            for (int mt = 0; mt < 4; mt++) {
                int r = wr * 64 + mt * 16 + (lane & 15);
                int c = ks * 2 + (lane >> 4);
                ldsm_x4(a[mt], sA + r * 128 + ((uint32_t)((c ^ (r & 7)) & 7) << 4));
            }
            #pragma unroll
            for (int mt = 0; mt < 4; mt++)
                #pragma unroll
                for (int n8 = 0; n8 < 4; n8++) {
                    mma_bf16(acc[mt][n8], a[mt], b0[n8 >> 1][(n8 & 1) * 2],
                             b0[n8 >> 1][(n8 & 1) * 2 + 1]);
                    mma_bf16(acc[mt][n8], a[mt], b1[n8 >> 1][(n8 & 1) * 2],
                             b1[n8 >> 1][(n8 & 1) * 2 + 1]);
                }
            #pragma unroll
            for (int mt = 0; mt < 4; mt++) {
                int r = wr * 64 + mt * 16 + (lane & 15);
                int c = ks * 2 + (lane >> 4);
                ldsm_x4(a[mt], sA + 16384 + r * 128 + ((uint32_t)((c ^ (r & 7)) & 7) << 4));
            }
            #pragma unroll
            for (int mt = 0; mt < 4; mt++)
                #pragma unroll
                for (int n8 = 0; n8 < 4; n8++)
                    mma_bf16(acc[mt][n8], a[mt], b0[n8 >> 1][(n8 & 1) * 2],
                             b0[n8 >> 1][(n8 & 1) * 2 + 1]);
        }
    }

    float* dst = g_mpart + (size_t)blockIdx.y * (H * D) + (size_t)k0 * 128;
    #pragma unroll
    for (int mt = 0; mt < 4; mt++)
        #pragma unroll
        for (int n8 = 0; n8 < 4; n8++)
            #pragma unroll
            for (int h = 0; h < 2; h++) {
                int r  = wr * 64 + mt * 16 + h * 8 + (lane >> 2);
                int cs = wc * 32 + n8 * 8 + (lane & 3) * 2;
                *(float2*)&dst[(size_t)r * 128 + cs] =
                    make_float2(acc[mt][n8][h * 2], acc[mt][n8][h * 2 + 1]);
            }
}

__global__ __launch_bounds__(256) void mreduce_kernel() {
    int i = blockIdx.x * 256 + threadIdx.x;
    if (i >= H * D / 4) return;
    float4 s = make_float4(0.f, 0.f, 0.f, 0.f);
    #pragma unroll
    for (int p = 0; p < 8; p++) {
        float4 v = ((const float4*)(g_mpart + (size_t)p * H * D))[i];
        s.x += v.x; s.y += v.y; s.z += v.z; s.w += v.w;
    }
    ((float4*)g_MT)[i] = s;
}

// ------------------ stage-1 persistent GEMM + argmax + rescore -------------
// grid (SGRID, 16): CTA owns segment blockIdx.y, iterates row tiles.
// B tile (256x128) loaded once; A (64x128) double-buffered via cp.async.
static constexpr int LIST_CAP = 512;
static constexpr int OFF_B    = 0;         // 65536
static constexpr int OFF_A    = 65536;     // 2 x 16384
static constexpr int OFF_BS   = 98304;     // 1024
static constexpr int OFF_RM4  = 99328;     // 1024
static constexpr int OFF_RMF  = 100352;    // 256
static constexpr int OFF_RKA  = 100608;    // 512
static constexpr int OFF_RKE  = 101120;    // 512
static constexpr int OFF_RC   = 101632;    // 256
static constexpr int OFF_CNT  = 101888;    // 16
static constexpr int OFF_LIST = 101904;    // 2048
static constexpr int S1_SMEM  = OFF_LIST + LIST_CAP * 4;   // 103952

__global__ __launch_bounds__(256, 2) void s1mma_kernel(const float* __restrict__ x,
                                                       const float* __restrict__ W1,
                                                       const float* __restrict__ b1) {
    extern __shared__ char sm[];
    const int tid  = threadIdx.x;
    const int lane = tid & 31;
    const int wid  = tid >> 5;
    const int wr   = wid >> 2;
    const int wc   = wid & 3;
    const int seg  = blockIdx.y;

    float* bs  = (float*)(sm + OFF_BS);
    float (*rm4)[4] = (float(*)[4])(sm + OFF_RM4);
    float* rmf = (float*)(sm + OFF_RMF);
    unsigned long long* rka = (unsigned long long*)(sm + OFF_RKA);
    unsigned long long* rke = (unsigned long long*)(sm + OFF_RKE);
    int* rc   = (int*)(sm + OFF_RC);
    int* cnt  = (int*)(sm + OFF_CNT);
    uint32_t* list = (uint32_t*)(sm + OFF_LIST);

    const uint32_t sBase = smem_u32(sm);
    const uint32_t sB = sBase + OFF_B;
    const uint32_t sA = sBase + OFF_A;

    bs[tid] = b1[seg * 256 + tid];

    // B tile: 256x128 bf16, loaded once
    const uint4* wb4 = (const uint4*)g_w1b + (size_t)seg * 256 * 16;
    #pragma unroll
    for (int i = 0; i < 16; i++) {
        int q = tid + i * 256;
        int r = q >> 4, c = q & 15;
        *(uint4*)(sm + OFF_B + r * 256 + ((c ^ (r & 7)) << 4)) = wb4[r * 16 + c];
    }

    // prefetch first A tile into buf 0
    {
        const uint4* src = (const uint4*)g_xb + (size_t)blockIdx.x * 64 * 16;
        #pragma unroll
        for (int i = 0; i < 4; i++) {
            int q = tid + i * 256;
            int r = q >> 4, c = q & 15;
            cpasync16(sA + r * 256 + ((c ^ (r & 7)) << 4), src + r * 16 + c);
        }
    }
    CP_COMMIT();

    int it = 0;
    for (int t = blockIdx.x; t < NTILE; t += SGRID, it++) {
        int tn = t + SGRID;
        if (tn < NTILE) {
            uint32_t dbuf = sA + ((it + 1) & 1) * 16384;
            const uint4* src = (const uint4*)g_xb + (size_t)tn * 64 * 16;
            #pragma unroll
            for (int i = 0; i < 4; i++) {
                int q = tid + i * 256;
                int r = q >> 4, c = q & 15;
                cpasync16(dbuf + r * 256 + ((c ^ (r & 7)) << 4), src + r * 16 + c);
            }
        }
        CP_COMMIT();
        CP_WAIT1();

        if (tid < 64) { rka[tid] = 0ull; rke[tid] = 0ull; rc[tid] = 0; }
        if (tid == 0) *cnt = 0;
        __syncthreads();

        const uint32_t sAc = sA + (it & 1) * 16384;

        float acc[2][8][4];
        #pragma unroll
        for (int mt = 0; mt < 2; mt++)
            #pragma unroll
            for (int nt = 0; nt < 8; nt++)
                #pragma unroll
                for (int e = 0; e < 4; e++) acc[mt][nt][e] = 0.f;

        #pragma unroll
        for (int ks = 0; ks < 8; ks++) {
            uint32_t a[2][4], b[4][4];
            #pragma unroll
            for (int mt = 0; mt < 2; mt++) {
                int r = wr * 32 + mt * 16 + (lane & 15);
                int c = ks * 2 + (lane >> 4);
                ldsm_x4(a[mt], sAc + r * 256 + ((uint32_t)(c ^ (r & 7)) << 4));
            }
            #pragma unroll
            for (int g = 0; g < 4; g++) {
                int r = wc * 64 + g * 16 + (lane & 7) + ((lane >> 4) << 3);
                int c = ks * 2 + ((lane >> 3) & 1);
                ldsm_x4(b[g], sB + r * 256 + ((uint32_t)(c ^ (r & 7)) << 4));
            }
            #pragma unroll
            for (int mt = 0; mt < 2; mt++)
                #pragma unroll
                for (int n8 = 0; n8 < 8; n8++)
                    mma_bf16(acc[mt][n8], a[mt], b[n8 >> 1][(n8 & 1) * 2],
                             b[n8 >> 1][(n8 & 1) * 2 + 1]);
        }

        // pass 1: approx row max
        const int q  = lane >> 2;
        const int qt = lane & 3;
        #pragma unroll
        for (int mt = 0; mt < 2; mt++)
            #pragma unroll
            for (int h = 0; h < 2; h++) {
                float vm = -3.402823466e+38f;
                #pragma unroll
                for (int nt = 0; nt < 8; nt++)
                    #pragma unroll
                    for (int c = 0; c < 2; c++) {
                        float v = acc[mt][nt][h * 2 + c] + bs[wc * 64 + nt * 8 + qt * 2 + c];
                        vm = fmaxf(vm, v);
                    }
                vm = fmaxf(vm, __shfl_xor_sync(0xffffffffu, vm, 1));
                vm = fmaxf(vm, __shfl_xor_sync(0xffffffffu, vm, 2));
                if (qt == 0) rm4[wr * 32 + mt * 16 + h * 8 + q][wc] = vm;
            }
        __syncthreads();
        if (tid < 64)
            rmf[tid] = fmaxf(fmaxf(rm4[tid][0], rm4[tid][1]),
                             fmaxf(rm4[tid][2], rm4[tid][3]));
        __syncthreads();

        // pass 2: candidates within TAU
        #pragma unroll
        for (int mt = 0; mt < 2; mt++)
            #pragma unroll
            for (int h = 0; h < 2; h++) {
                int rl = wr * 32 + mt * 16 + h * 8 + q;
                float thr = rmf[rl] - TAU;
                #pragma unroll
                for (int nt = 0; nt < 8; nt++)
                    #pragma unroll
                    for (int c = 0; c < 2; c++) {
                        int cs = wc * 64 + nt * 8 + qt * 2 + c;
                        float v = acc[mt][nt][h * 2 + c] + bs[cs];
                        if (v >= thr) {
                            atomicAdd(&rc[rl], 1);
                            unsigned long long key =
                                ((unsigned long long)ford(v) << 32) | (uint32_t)(255 - cs);
                            atomicMax(&rka[rl], key);
                            int p = atomicAdd(cnt, 1);
                            if (p < LIST_CAP) list[p] = ((uint32_t)rl << 8) | (uint32_t)cs;
                        }
                    }
            }
        __syncthreads();

        // unambiguous rows: provably exact
        if (tid < 64 && rc[tid] == 1) {
            int col = 255 - (int)(rka[tid] & 0xFFu);
            g_idx[(size_t)(t * 64 + tid) * NSEG + seg] = col;
        }

        // ambiguous rows: exact fp32 rescore
        int n = *cnt;
        if (n > LIST_CAP) n = LIST_CAP;
        for (int i = wid; i < n; i += 8) {
            uint32_t e = list[i];
            int rl = e >> 8, cs = e & 255;
            if (rc[rl] < 2) continue;
            const float4* xr = (const float4*)(x  + (size_t)(t * 64 + rl) * 128);
            const float4* wv = (const float4*)(W1 + (size_t)(seg * 256 + cs) * 128);
            float4 xa = __ldg(&xr[lane]);
            float4 wa = __ldg(&wv[lane]);
            float s = xa.x * wa.x + xa.y * wa.y + xa.z * wa.z + xa.w * wa.w;
            #pragma unroll
            for (int off = 16; off > 0; off >>= 1)
                s += __shfl_xor_sync(0xffffffffu, s, off);
            if (lane == 0) {
                float val = s + bs[cs];
                unsigned long long key =
                    ((unsigned long long)ford(val) << 32) | (uint32_t)(255 - cs);
                atomicMax(&rke[rl], key);
            }
        }
        __syncthreads();
        if (tid < 64 && rc[tid] > 1) {
            int col = 255 - (int)(rke[tid] & 0xFFu);
            g_idx[(size_t)(t * 64 + tid) * NSEG + seg] = col;
        }
        __syncthreads();
    }
}

// --------------------------------- gather ---------------------------------
__global__ __launch_bounds__(128) void gather_kernel(float* __restrict__ out) {
    const int rowbase = blockIdx.x * 16;
    const int t = threadIdx.x;
    __shared__ int sidx[16][16];
    #pragma unroll
    for (int qq = t; qq < 256; qq += 128)
        sidx[qq >> 4][qq & 15] = g_idx[(size_t)(rowbase + (qq >> 4)) * NSEG + (qq & 15)];
    __syncthreads();

    const float cv = g_c[t];
    float acc[16];
    #pragma unroll
    for (int r = 0; r < 16; r++) acc[r] = cv;

    #pragma unroll
    for (int s = 0; s < NSEG; s++) {
        #pragma unroll
        for (int r = 0; r < 16; r++) {
            int col = (s << 8) + sidx[r][s];
            acc[r] += g_MT[(size_t)col * D + t];
        }
    }
    #pragma unroll
    for (int r = 0; r < 16; r++)
        out[(size_t)(rowbase + r) * D + t] = acc[r];
}

// ------------------------------- launcher ----------------------------------
extern "C" void kernel_launch(void* const* d_in, const int* in_sizes, int n_in,
                              void* d_out, int out_size) {
    const float* x  = (const float*)d_in[0];
    const float* W1 = (const float*)d_in[1];
    const float* b1 = (const float*)d_in[2];
    const float* W2 = (const float*)d_in[3];
    const float* b2 = (const float*)d_in[4];
    const float* W3 = (const float*)d_in[5];
    const float* b3 = (const float*)d_in[6];
    float* out = (float*)d_out;
    const int B = in_sizes[0] / D;   // 32768

    void *p_xb = nullptr, *p_w1b = nullptr;
    cudaGetSymbolAddress(&p_xb,  g_xb);
    cudaGetSymbolAddress(&p_w1b, g_w1b);

    cudaFuncSetAttribute(s1mma_kernel,
                         cudaFuncAttributeMaxDynamicSharedMemorySize, S1_SMEM);
    cudaFuncSetAttribute(mm2_kernel,
                         cudaFuncAttributeMaxDynamicSharedMemorySize, MM_SMEM);

    convertb_kernel<<<(B * D / 8 + 255) / 256, 256>>>(x,  (__nv_bfloat16*)p_xb,  B * D / 8);
    convertb_kernel<<<(H * D / 8 + 255) / 256, 256>>>(W1, (__nv_bfloat16*)p_w1b, H * D / 8);
    w3split_kernel<<<(H * D / 2 + 255) / 256, 256>>>(W3);

    s1mma_kernel<<<dim3(SGRID, NSEG), 256, S1_SMEM>>>(x, W1, b1);   // 4th launch

    w2split_kernel<<<dim3(H / 64, H / 64), 256>>>(W2);
    c_kernel<<<D, 256>>>(W3, b2, b3);
    mm2_kernel<<<dim3(32, 8), 256, MM_SMEM>>>();
    mreduce_kernel<<<(H * D / 4 + 255) / 256, 256>>>();

    gather_kernel<<<B / 16, 128>>>(out);
}

// round 9
// speedup vs baseline: 3.4711x; 1.0882x over previous
#include <cuda_runtime.h>
#include <cuda_bf16.h>
#include <cstdint>
#include <cstddef>
#include <cfloat>

// ---------------------------------------------------------------------------
// Sbox16: out = c + sum_seg M[:, seg*256 + argmax_seg(x@W1^T + b1)]
//   M = W3@W2 (128x4096), c = W3@b2 + b3
// R9: s1 epilogue rebuilt around register top-2 (no smem atomics in the
//     common path, 5 barriers/iter). Ambiguous rows only (~17%) hit the
//     candidate list + exact fp32 rescore.
// ---------------------------------------------------------------------------

static constexpr int BMAX = 32768;
static constexpr int D    = 128;
static constexpr int H    = 4096;
static constexpr int NSEG = 16;
static constexpr float TAU = 0.13f;
static constexpr int NTILE = BMAX / 64;      // 512 row tiles
static constexpr int SGRID = 37;             // CTAs per segment (2 waves @ occ2)

__device__ __nv_bfloat16 g_xb [BMAX * D];
__device__ __nv_bfloat16 g_w1b[H * D];
__device__ __nv_bfloat16 g_w2t[2 * (size_t)H * H];
__device__ __nv_bfloat16 g_w3b[2 * H * D];
__device__ float g_mpart[8 * H * D];
__device__ float g_MT [H * D];
__device__ float g_c  [D];
__device__ int   g_idx[BMAX * NSEG];

// ------------------------------- ptx helpers -------------------------------
__device__ __forceinline__ uint32_t smem_u32(const void* p) {
    uint32_t a;
    asm("{ .reg .u64 t; cvta.to.shared.u64 t, %1; cvt.u32.u64 %0, t; }" : "=r"(a) : "l"(p));
    return a;
}
__device__ __forceinline__ void ldsm_x4(uint32_t* r, uint32_t addr) {
    asm volatile("ldmatrix.sync.aligned.m8n8.x4.shared.b16 {%0,%1,%2,%3}, [%4];"
                 : "=r"(r[0]), "=r"(r[1]), "=r"(r[2]), "=r"(r[3]) : "r"(addr));
}
__device__ __forceinline__ void mma_bf16(float* d, const uint32_t* a,
                                         uint32_t b0, uint32_t b1) {
    asm volatile("mma.sync.aligned.m16n8k16.row.col.f32.bf16.bf16.f32 "
                 "{%0,%1,%2,%3}, {%4,%5,%6,%7}, {%8,%9}, {%0,%1,%2,%3};"
                 : "+f"(d[0]), "+f"(d[1]), "+f"(d[2]), "+f"(d[3])
                 : "r"(a[0]), "r"(a[1]), "r"(a[2]), "r"(a[3]), "r"(b0), "r"(b1));
}
__device__ __forceinline__ uint32_t ford(float f) {
    uint32_t u = __float_as_uint(f);
    return (u & 0x80000000u) ? ~u : (u | 0x80000000u);
}
__device__ __forceinline__ float iford(uint32_t u) {
    uint32_t v = (u & 0x80000000u) ? (u & 0x7FFFFFFFu) : ~u;
    return __uint_as_float(v);
}
__device__ __forceinline__ void cpasync16(uint32_t dst, const void* src) {
    asm volatile("cp.async.cg.shared.global [%0], [%1], 16;" :: "r"(dst), "l"(src));
}
#define CP_COMMIT() asm volatile("cp.async.commit_group;" ::: "memory")
#define CP_WAIT1()  asm volatile("cp.async.wait_group 1;" ::: "memory")

// ------------------------------ prepasses ----------------------------------
__global__ __launch_bounds__(256) void convertb_kernel(const float* __restrict__ src,
                                                       __nv_bfloat16* __restrict__ dst,
                                                       int n8) {
    int i = blockIdx.x * 256 + threadIdx.x;
    if (i >= n8) return;
    const float4* s4 = (const float4*)src;
    float4 a = s4[i * 2], b = s4[i * 2 + 1];
    __nv_bfloat162 p0 = __float22bfloat162_rn(make_float2(a.x, a.y));
    __nv_bfloat162 p1 = __float22bfloat162_rn(make_float2(a.z, a.w));
    __nv_bfloat162 p2 = __float22bfloat162_rn(make_float2(b.x, b.y));
    __nv_bfloat162 p3 = __float22bfloat162_rn(make_float2(b.z, b.w));
    uint4 o;
    o.x = *(uint32_t*)&p0; o.y = *(uint32_t*)&p1;
    o.z = *(uint32_t*)&p2; o.w = *(uint32_t*)&p3;
    ((uint4*)dst)[i] = o;
}

__global__ __launch_bounds__(256) void w3split_kernel(const float* __restrict__ W3) {
    int i = blockIdx.x * 256 + threadIdx.x;
    if (i >= H * D / 2) return;
    float2 v = ((const float2*)W3)[i];
    __nv_bfloat16 a0 = __float2bfloat16(v.x);
    __nv_bfloat16 b0 = __float2bfloat16(v.x - __bfloat162float(a0));
    __nv_bfloat16 a1 = __float2bfloat16(v.y);
    __nv_bfloat16 b1 = __float2bfloat16(v.y - __bfloat162float(a1));
    __nv_bfloat162 pa = {a0, a1}, pb = {b0, b1};
    ((__nv_bfloat162*)g_w3b)[i] = pa;
    ((__nv_bfloat162*)g_w3b)[H * D / 2 + i] = pb;
}

// W2 transpose + 2-term split, 64x64 fp32 tiles, stride 68 floats (16B-aligned).
__global__ __launch_bounds__(256) void w2split_kernel(const float* __restrict__ W2) {
    __shared__ float tile[64][68];
    const int tid = threadIdx.x;
    const int j0 = blockIdx.x * 64;
    const int k0 = blockIdx.y * 64;
    #pragma unroll
    for (int p = 0; p < 4; p++) {
        int q = tid + p * 256;
        int r = q >> 4, c = (q & 15) * 4;
        *(float4*)&tile[r][c] = *(const float4*)&W2[(size_t)(j0 + r) * H + k0 + c];
    }
    __syncthreads();
    #pragma unroll
    for (int p = 0; p < 2; p++) {
        int q = tid + p * 256;
        int k = q >> 3, cs = (q & 7) * 8;
        __nv_bfloat16 ma[8], mb[8];
        #pragma unroll
        for (int e = 0; e < 8; e++) {
            float v = tile[cs + e][k];
            ma[e] = __float2bfloat16(v);
            mb[e] = __float2bfloat16(v - __bfloat162float(ma[e]));
        }
        size_t off = (size_t)(k0 + k) * H + j0 + cs;
        *(uint4*)(g_w2t + off) = *(uint4*)ma;
        *(uint4*)(g_w2t + (size_t)H * H + off) = *(uint4*)mb;
    }
}

// ---------------------------------- c ------------------------------------
__global__ void c_kernel(const float* __restrict__ W3,
                         const float* __restrict__ b2,
                         const float* __restrict__ b3) {
    const int i = blockIdx.x;
    float s = 0.f;
    for (int j = threadIdx.x; j < H; j += 256)
        s += W3[(size_t)i * H + j] * b2[j];
    __shared__ float red[256];
    red[threadIdx.x] = s;
    __syncthreads();
    for (int o = 128; o > 0; o >>= 1) {
        if (threadIdx.x < o) red[threadIdx.x] += red[threadIdx.x + o];
        __syncthreads();
    }
    if (threadIdx.x == 0) g_c[i] = red[0] + b3[i];
}

// ----------------- M via mma.sync: MT[k][i] = sum_j W2[j][k]W3[i][j] --------
static constexpr int MM_SMEM = 65536;

__global__ __launch_bounds__(256, 2) void mm2_kernel() {
    extern __shared__ char sm[];
    const int tid  = threadIdx.x;
    const int lane = tid & 31;
    const int wid  = tid >> 5;
    const int wr   = wid >> 2;
    const int wc   = wid & 3;
    const int k0   = blockIdx.x * 128;
    const int j0   = blockIdx.y * 512;

    const uint32_t sA = smem_u32(sm);
    const uint32_t sB = sA + 32768;

    float acc[4][4][4];
    #pragma unroll
    for (int mt = 0; mt < 4; mt++)
        #pragma unroll
        for (int nt = 0; nt < 4; nt++)
            #pragma unroll
            for (int e = 0; e < 4; e++) acc[mt][nt][e] = 0.f;

    for (int jc = 0; jc < 8; jc++) {
        __syncthreads();
        #pragma unroll
        for (int t = 0; t < 2; t++) {
            const __nv_bfloat16* srcA = g_w2t + (size_t)t * H * H
                                      + (size_t)k0 * H + j0 + jc * 64;
            #pragma unroll
            for (int i = 0; i < 4; i++) {
                int q = tid + i * 256;
                int r = q >> 3, c = q & 7;
                *(uint4*)(sm + t * 16384 + r * 128 + (((c ^ (r & 7)) & 7) << 4)) =
                    *(const uint4*)(srcA + (size_t)r * H + c * 8);
            }
        }
        #pragma unroll
        for (int t = 0; t < 2; t++) {
            const __nv_bfloat16* srcB = g_w3b + (size_t)t * H * D
                                      + j0 + jc * 64;
            #pragma unroll
            for (int i = 0; i < 4; i++) {
                int q = tid + i * 256;
                int r = q >> 3, c = q & 7;
                *(uint4*)(sm + 32768 + t * 16384 + r * 128 + (((c ^ (r & 7)) & 7) << 4)) =
                    *(const uint4*)(srcB + (size_t)r * H + c * 8);
            }
        }
        __syncthreads();

        #pragma unroll
        for (int ks = 0; ks < 4; ks++) {
            uint32_t b0[2][4], b1[2][4], a[4][4];
            #pragma unroll
            for (int g = 0; g < 2; g++) {
                int r = wc * 32 + g * 16 + (lane & 7) + ((lane >> 4) << 3);
                int c = ks * 2 + ((lane >> 3) & 1);
                uint32_t sw = (uint32_t)((c ^ (r & 7)) & 7) << 4;
                ldsm_x4(b0[g], sB + r * 128 + sw);
                ldsm_x4(b1[g], sB + 16384 + r * 128 + sw);
            }
            #pragma unroll
            for (int mt = 0; mt < 4; mt++) {
                int r = wr * 64 + mt * 16 + (lane & 15);
                int c = ks * 2 + (lane >> 4);
                ldsm_x4(a[mt], sA + r * 128 + ((uint32_t)((c ^ (r & 7)) & 7) << 4));
            }
            #pragma unroll
            for (int mt = 0; mt < 4; mt++)
                #pragma unroll
                for (int n8 = 0; n8 < 4; n8++) {
                    mma_bf16(acc[mt][n8], a[mt], b0[n8 >> 1][(n8 & 1) * 2],
                             b0[n8 >> 1][(n8 & 1) * 2 + 1]);
                    mma_bf16(acc[mt][n8], a[mt], b1[n8 >> 1][(n8 & 1) * 2],
                             b1[n8 >> 1][(n8 & 1) * 2 + 1]);
                }
            #pragma unroll
            for (int mt = 0; mt < 4; mt++) {
                int r = wr * 64 + mt * 16 + (lane & 15);
                int c = ks * 2 + (lane >> 4);
                ldsm_x4(a[mt], sA + 16384 + r * 128 + ((uint32_t)((c ^ (r & 7)) & 7) << 4));
            }
            #pragma unroll
            for (int mt = 0; mt < 4; mt++)
                #pragma unroll
                for (int n8 = 0; n8 < 4; n8++)
                    mma_bf16(acc[mt][n8], a[mt], b0[n8 >> 1][(n8 & 1) * 2],
                             b0[n8 >> 1][(n8 & 1) * 2 + 1]);
        }
    }

    float* dst = g_mpart + (size_t)blockIdx.y * (H * D) + (size_t)k0 * 128;
    #pragma unroll
    for (int mt = 0; mt < 4; mt++)
        #pragma unroll
        for (int n8 = 0; n8 < 4; n8++)
            #pragma unroll
            for (int h = 0; h < 2; h++) {
                int r  = wr * 64 + mt * 16 + h * 8 + (lane >> 2);
                int cs = wc * 32 + n8 * 8 + (lane & 3) * 2;
                *(float2*)&dst[(size_t)r * 128 + cs] =
                    make_float2(acc[mt][n8][h * 2], acc[mt][n8][h * 2 + 1]);
            }
}

__global__ __launch_bounds__(256) void mreduce_kernel() {
    int i = blockIdx.x * 256 + threadIdx.x;
    if (i >= H * D / 4) return;
    float4 s = make_float4(0.f, 0.f, 0.f, 0.f);
    #pragma unroll
    for (int p = 0; p < 8; p++) {
        float4 v = ((const float4*)(g_mpart + (size_t)p * H * D))[i];
        s.x += v.x; s.y += v.y; s.z += v.z; s.w += v.w;
    }
    ((float4*)g_MT)[i] = s;
}

// ------------------ stage-1 persistent GEMM + top-2 epilogue ----------------
// grid (SGRID, 16). B tile (256x128) loaded once; A (64x128) double-buffered.
// Register top-2 per row -> direct write when margin > TAU; ambiguous rows
// only hit the candidate list + exact fp32 rescore.
static constexpr int LIST_CAP = 512;
static constexpr int OFF_B    = 0;         // 65536
static constexpr int OFF_A    = 65536;     // 2 x 16384 -> 98304
static constexpr int OFF_BS   = 98304;     // 1024
static constexpr int OFF_RKEY = 99328;     // u64[64][4] = 2048
static constexpr int OFF_RV2  = 101376;    // f32[64][4] = 1024
static constexpr int OFF_RMF  = 102400;    // f32[64]    = 256
static constexpr int OFF_FLAG = 102656;    // int[64]    = 256
static constexpr int OFF_RKE  = 102912;    // u64[64]    = 512
static constexpr int OFF_CNT  = 103424;    // 16
static constexpr int OFF_LIST = 103440;    // 2048
static constexpr int S1_SMEM  = OFF_LIST + LIST_CAP * 4;   // 105488

__global__ __launch_bounds__(256, 2) void s1mma_kernel(const float* __restrict__ x,
                                                       const float* __restrict__ W1,
                                                       const float* __restrict__ b1) {
    extern __shared__ char sm[];
    const int tid  = threadIdx.x;
    const int lane = tid & 31;
    const int wid  = tid >> 5;
    const int wr   = wid >> 2;
    const int wc   = wid & 3;
    const int seg  = blockIdx.y;

    float* bs  = (float*)(sm + OFF_BS);
    unsigned long long (*rkey)[4] = (unsigned long long(*)[4])(sm + OFF_RKEY);
    float (*rv2)[4] = (float(*)[4])(sm + OFF_RV2);
    float* rmf = (float*)(sm + OFF_RMF);
    int* flag  = (int*)(sm + OFF_FLAG);
    unsigned long long* rke = (unsigned long long*)(sm + OFF_RKE);
    int* cnt   = (int*)(sm + OFF_CNT);
    uint32_t* list = (uint32_t*)(sm + OFF_LIST);

    const uint32_t sBase = smem_u32(sm);
    const uint32_t sB = sBase + OFF_B;
    const uint32_t sA = sBase + OFF_A;

    bs[tid] = b1[seg * 256 + tid];

    // B tile: 256x128 bf16, loaded once
    const uint4* wb4 = (const uint4*)g_w1b + (size_t)seg * 256 * 16;
    #pragma unroll
    for (int i = 0; i < 16; i++) {
        int qq = tid + i * 256;
        int r = qq >> 4, c = qq & 15;
        *(uint4*)(sm + OFF_B + r * 256 + ((c ^ (r & 7)) << 4)) = wb4[r * 16 + c];
    }

    // prefetch first A tile into buf 0
    {
        const uint4* src = (const uint4*)g_xb + (size_t)blockIdx.x * 64 * 16;
        #pragma unroll
        for (int i = 0; i < 4; i++) {
            int qq = tid + i * 256;
            int r = qq >> 4, c = qq & 15;
            cpasync16(sA + r * 256 + ((c ^ (r & 7)) << 4), src + r * 16 + c);
        }
    }
    CP_COMMIT();

    int it = 0;
    for (int t = blockIdx.x; t < NTILE; t += SGRID, it++) {
        int tn = t + SGRID;
        if (tn < NTILE) {
            uint32_t dbuf = sA + ((it + 1) & 1) * 16384;
            const uint4* src = (const uint4*)g_xb + (size_t)tn * 64 * 16;
            #pragma unroll
            for (int i = 0; i < 4; i++) {
                int qq = tid + i * 256;
                int r = qq >> 4, c = qq & 15;
                cpasync16(dbuf + r * 256 + ((c ^ (r & 7)) << 4), src + r * 16 + c);
            }
        }
        CP_COMMIT();
        CP_WAIT1();
        __syncthreads();                               // sync0: A buf visible

        const uint32_t sAc = sA + (it & 1) * 16384;

        float acc[2][8][4];
        #pragma unroll
        for (int mt = 0; mt < 2; mt++)
            #pragma unroll
            for (int nt = 0; nt < 8; nt++)
                #pragma unroll
                for (int e = 0; e < 4; e++) acc[mt][nt][e] = 0.f;

        #pragma unroll
        for (int ks = 0; ks < 8; ks++) {
            uint32_t a[2][4], b[4][4];
            #pragma unroll
            for (int mt = 0; mt < 2; mt++) {
                int r = wr * 32 + mt * 16 + (lane & 15);
                int c = ks * 2 + (lane >> 4);
                ldsm_x4(a[mt], sAc + r * 256 + ((uint32_t)(c ^ (r & 7)) << 4));
            }
            #pragma unroll
            for (int g = 0; g < 4; g++) {
                int r = wc * 64 + g * 16 + (lane & 7) + ((lane >> 4) << 3);
                int c = ks * 2 + ((lane >> 3) & 1);
                ldsm_x4(b[g], sB + r * 256 + ((uint32_t)(c ^ (r & 7)) << 4));
            }
            #pragma unroll
            for (int mt = 0; mt < 2; mt++)
                #pragma unroll
                for (int n8 = 0; n8 < 8; n8++)
                    mma_bf16(acc[mt][n8], a[mt], b[n8 >> 1][(n8 & 1) * 2],
                             b[n8 >> 1][(n8 & 1) * 2 + 1]);
        }

        // ---- register top-2 per row per quadrant ----
        const int q  = lane >> 2;
        const int qt = lane & 3;
        #pragma unroll
        for (int mt = 0; mt < 2; mt++)
            #pragma unroll
            for (int h = 0; h < 2; h++) {
                float v1 = -FLT_MAX, v2 = -FLT_MAX;
                int i1 = 0;
                #pragma unroll
                for (int nt = 0; nt < 8; nt++)
                    #pragma unroll
                    for (int c2 = 0; c2 < 2; c2++) {
                        int cs = wc * 64 + nt * 8 + qt * 2 + c2;
                        float v = acc[mt][nt][h * 2 + c2] + bs[cs];
                        if (v > v1) { v2 = v1; v1 = v; i1 = cs; }
                        else if (v > v2) v2 = v;
                    }
                #pragma unroll
                for (int off = 1; off <= 2; off <<= 1) {
                    float ov1 = __shfl_xor_sync(0xffffffffu, v1, off);
                    int   oi1 = __shfl_xor_sync(0xffffffffu, i1, off);
                    float ov2 = __shfl_xor_sync(0xffffffffu, v2, off);
                    bool owin = (ov1 > v1) || (ov1 == v1 && oi1 < i1);
                    if (owin) { v2 = fmaxf(v1, ov2); v1 = ov1; i1 = oi1; }
                    else      { v2 = fmaxf(v2, ov1); }
                }
                if (qt == 0) {
                    int rl = wr * 32 + mt * 16 + h * 8 + q;
                    rkey[rl][wc] =
                        ((unsigned long long)ford(v1) << 32) | (uint32_t)(255 - i1);
                    rv2[rl][wc] = v2;
                }
            }
        __syncthreads();                               // sync1

        // ---- merge 4 quadrants, classify, direct-write unambiguous ----
        if (tid < 64) {
            unsigned long long K = rkey[tid][0];
            #pragma unroll
            for (int q2 = 1; q2 < 4; q2++) {
                unsigned long long kq = rkey[tid][q2];
                if (kq > K) K = kq;
            }
            float v1 = iford((uint32_t)(K >> 32));
            float s2 = -FLT_MAX;
            #pragma unroll
            for (int q2 = 0; q2 < 4; q2++) {
                unsigned long long kq = rkey[tid][q2];
                float cv = (kq == K) ? rv2[tid][q2] : iford((uint32_t)(kq >> 32));
                s2 = fmaxf(s2, cv);
            }
            int fl = (v1 - s2 <= TAU) ? 1 : 0;
            flag[tid] = fl;
            if (!fl) {
                g_idx[(size_t)(t * 64 + tid) * NSEG + seg] = 255 - (int)(K & 0xFFu);
            } else {
                rmf[tid] = v1;
                rke[tid] = 0ull;
            }
        }
        if (tid == 0) *cnt = 0;
        __syncthreads();                               // sync2

        // ---- candidate collection for ambiguous rows only ----
        #pragma unroll
        for (int mt = 0; mt < 2; mt++)
            #pragma unroll
            for (int h = 0; h < 2; h++) {
                int rl = wr * 32 + mt * 16 + h * 8 + q;
                if (flag[rl]) {
                    float thr = rmf[rl] - TAU;
                    #pragma unroll
                    for (int nt = 0; nt < 8; nt++)
                        #pragma unroll
                        for (int c2 = 0; c2 < 2; c2++) {
                            int cs = wc * 64 + nt * 8 + qt * 2 + c2;
                            float v = acc[mt][nt][h * 2 + c2] + bs[cs];
                            if (v >= thr) {
                                int p = atomicAdd(cnt, 1);
                                if (p < LIST_CAP)
                                    list[p] = ((uint32_t)rl << 8) | (uint32_t)cs;
                            }
                        }
                }
            }
        __syncthreads();                               // sync3

        // ---- exact fp32 rescore of ambiguous candidates ----
        int n = *cnt;
        if (n > LIST_CAP) n = LIST_CAP;
        for (int i = wid; i < n; i += 8) {
            uint32_t e = list[i];
            int rl = e >> 8, cs = e & 255;
            const float4* xr = (const float4*)(x  + (size_t)(t * 64 + rl) * 128);
            const float4* wv = (const float4*)(W1 + (size_t)(seg * 256 + cs) * 128);
            float4 xa = __ldg(&xr[lane]);
            float4 wa = __ldg(&wv[lane]);
            float s = xa.x * wa.x + xa.y * wa.y + xa.z * wa.z + xa.w * wa.w;
            #pragma unroll
            for (int off = 16; off > 0; off >>= 1)
                s += __shfl_xor_sync(0xffffffffu, s, off);
            if (lane == 0) {
                float val = s + bs[cs];
                unsigned long long key =
                    ((unsigned long long)ford(val) << 32) | (uint32_t)(255 - cs);
                atomicMax(&rke[rl], key);
            }
        }
        __syncthreads();                               // sync4
        if (tid < 64 && flag[tid]) {
            g_idx[(size_t)(t * 64 + tid) * NSEG + seg] = 255 - (int)(rke[tid] & 0xFFu);
        }
    }
}

// --------------------------------- gather ---------------------------------
__global__ __launch_bounds__(128) void gather_kernel(float* __restrict__ out) {
    const int rowbase = blockIdx.x * 16;
    const int t = threadIdx.x;
    __shared__ int sidx[16][16];
    #pragma unroll
    for (int qq = t; qq < 256; qq += 128)
        sidx[qq >> 4][qq & 15] = g_idx[(size_t)(rowbase + (qq >> 4)) * NSEG + (qq & 15)];
    __syncthreads();

    const float cv = g_c[t];
    float acc[16];
    #pragma unroll
    for (int r = 0; r < 16; r++) acc[r] = cv;

    #pragma unroll
    for (int s = 0; s < NSEG; s++) {
        #pragma unroll
        for (int r = 0; r < 16; r++) {
            int col = (s << 8) + sidx[r][s];
            acc[r] += g_MT[(size_t)col * D + t];
        }
    }
    #pragma unroll
    for (int r = 0; r < 16; r++)
        out[(size_t)(rowbase + r) * D + t] = acc[r];
}

// ------------------------------- launcher ----------------------------------
extern "C" void kernel_launch(void* const* d_in, const int* in_sizes, int n_in,
                              void* d_out, int out_size) {
    const float* x  = (const float*)d_in[0];
    const float* W1 = (const float*)d_in[1];
    const float* b1 = (const float*)d_in[2];
    const float* W2 = (const float*)d_in[3];
    const float* b2 = (const float*)d_in[4];
    const float* W3 = (const float*)d_in[5];
    const float* b3 = (const float*)d_in[6];
    float* out = (float*)d_out;
    const int B = in_sizes[0] / D;   // 32768

    void *p_xb = nullptr, *p_w1b = nullptr;
    cudaGetSymbolAddress(&p_xb,  g_xb);
    cudaGetSymbolAddress(&p_w1b, g_w1b);

    cudaFuncSetAttribute(s1mma_kernel,
                         cudaFuncAttributeMaxDynamicSharedMemorySize, S1_SMEM);
    cudaFuncSetAttribute(mm2_kernel,
                         cudaFuncAttributeMaxDynamicSharedMemorySize, MM_SMEM);

    convertb_kernel<<<(B * D / 8 + 255) / 256, 256>>>(x,  (__nv_bfloat16*)p_xb,  B * D / 8);
    convertb_kernel<<<(H * D / 8 + 255) / 256, 256>>>(W1, (__nv_bfloat16*)p_w1b, H * D / 8);
    w3split_kernel<<<(H * D / 2 + 255) / 256, 256>>>(W3);

    s1mma_kernel<<<dim3(SGRID, NSEG), 256, S1_SMEM>>>(x, W1, b1);   // 4th launch

    w2split_kernel<<<dim3(H / 64, H / 64), 256>>>(W2);
    c_kernel<<<D, 256>>>(W3, b2, b3);
    mm2_kernel<<<dim3(32, 8), 256, MM_SMEM>>>();
    mreduce_kernel<<<(H * D / 4 + 255) / 256, 256>>>();

    gather_kernel<<<B / 16, 128>>>(out);
}